// round 4
// baseline (speedup 1.0000x reference)
#include <cuda_runtime.h>

// ---------------- problem constants ----------------
#define THW   4800               // 16*15*20
#define CIN   512
#define KTOT  13824              // 27*512
#define NPROP 86400              // THW*18
#define NM    38400              // 8*THW  (GEMM M)
#define OUT_PROB 16800           // rois = 8*300*7
#define OUT_BBOX (16800 + 1382400)

// ---------------- static scratch (no cudaMalloc allowed) -------------------
__device__ float    g_wt[KTOT * 512];      // conv weights  [k = tap*512+ci][cout]
__device__ float    g_whead[512 * 144];    // head weights  [k][n]  n: 0..35 cls, 36..143 bbox
__device__ float    g_rpn[NM * 512];       // relu(conv)    [m][cout]
__device__ float    g_cls[8 * 36 * THW];   // cls scores    [b][c][pos]
__device__ unsigned g_okey[8 * NPROP];     // ordered score bits
__device__ float    g_props[8 * NPROP * 6];

// ---------------- helpers ----------------
__device__ __forceinline__ unsigned okey(float f) {
    unsigned u = __float_as_uint(f);
    return (u & 0x80000000u) ? ~u : (u | 0x80000000u);
}
__device__ __forceinline__ void fma2(unsigned long long& d,
                                     unsigned long long a, unsigned long long b) {
    asm("fma.rn.f32x2 %0, %1, %2, %0;" : "+l"(d) : "l"(a), "l"(b));
}
__device__ __forceinline__ unsigned long long add2(unsigned long long a,
                                                   unsigned long long b) {
    unsigned long long r;
    asm("add.rn.f32x2 %0, %1, %2;" : "=l"(r) : "l"(a), "l"(b));
    return r;
}
__device__ __forceinline__ unsigned long long neg2(unsigned long long a) {
    return a ^ 0x8000000080000000ULL;
}
__device__ __forceinline__ unsigned long long dup2(float a) {
    unsigned long long r;
    asm("mov.b64 %0, {%1, %1};" : "=l"(r) : "f"(a));
    return r;
}
__device__ __forceinline__ unsigned long long pack2(float a, float b) {
    unsigned long long r;
    asm("mov.b64 %0, {%1, %2};" : "=l"(r) : "f"(a), "f"(b));
    return r;
}
__device__ __forceinline__ void unpack2(unsigned long long v, float& lo, float& hi) {
    asm("mov.b64 {%0, %1}, %2;" : "=f"(lo), "=f"(hi) : "l"(v));
}

// ---------------- kernel: transpose conv weights ---------------------------
__global__ void k_wt(const float* __restrict__ w) {
    int i = blockIdx.x * 256 + threadIdx.x;
    if (i >= KTOT * 512) return;
    int co  = i & 511;
    int k   = i >> 9;
    int tap = k >> 9;
    int ci  = k & 511;
    g_wt[i] = __ldg(&w[(co * 512 + ci) * 27 + tap]);
}

// ---------------- kernel: build head weight matrix -------------------------
__global__ void k_whead(const float* __restrict__ wc, const float* __restrict__ wb) {
    int i = blockIdx.x * 256 + threadIdx.x;
    if (i >= 512 * 144) return;
    int k = i / 144;
    int n = i - k * 144;
    g_whead[i] = (n < 36) ? __ldg(&wc[n * 512 + k]) : __ldg(&wb[(n - 36) * 512 + k]);
}

// ---------------- kernel: 3x3x3 conv + bias + relu (fp32x2 SGEMM, Kahan) ---
// M=38400 (grid.x=300), N=512 (grid.y=4), K=13824 (1728 BK=8 slices)
// Inner acc runs 8 slices (64 adds), then Kahan-merged into outer+comp.
__global__ __launch_bounds__(256, 1) void k_conv(const float* __restrict__ x,
                                                 const float* __restrict__ bias) {
    __shared__ float As[2][8][128];
    __shared__ float Bs[2][8][128];

    const int tid = threadIdx.x;
    const int m0  = blockIdx.x * 128;
    const int n0  = blockIdx.y * 128;
    const int lk  = tid >> 5;                // 0..7   load k-row
    const int lm  = tid & 31;                // 0..31  load m-col base
    const int tx  = tid & 15;
    const int ty  = tid >> 4;

    // per-thread A source coordinates (4 m each)
    int xb[4], pk[4];
    #pragma unroll
    for (int j = 0; j < 4; ++j) {
        int m   = m0 + lm + 32 * j;
        int b   = m / THW;
        int pos = m - b * THW;
        int t   = pos / 300;
        int r   = pos - t * 300;
        int h   = r / 20;
        int w   = r - h * 20;
        xb[j] = b * (CIN * THW);
        pk[j] = t | (h << 8) | (w << 16);
    }

    int    aoff[4];
    float  ra[4];
    float4 rb;
    unsigned long long acc[8][4];     // inner chunk accumulator
    unsigned long long oac[8][4];     // outer Kahan sum
    unsigned long long cmp[8][4];     // Kahan compensation
    #pragma unroll
    for (int i = 0; i < 8; ++i)
        #pragma unroll
        for (int p = 0; p < 4; ++p) { acc[i][p] = 0ull; oac[i][p] = 0ull; cmp[i][p] = 0ull; }

    // ---- prologue: slice 0 ----
    {
        int dt = -1, dh = -1, dw = -1;
        #pragma unroll
        for (int j = 0; j < 4; ++j) {
            int t = (pk[j] & 255) + dt;
            int h = ((pk[j] >> 8) & 255) + dh;
            int w = ((pk[j] >> 16) & 255) + dw;
            bool ok = (unsigned)t < 16u && (unsigned)h < 15u && (unsigned)w < 20u;
            aoff[j] = ok ? ((t * 15 + h) * 20 + w) : -1;
        }
        int abase = lk * THW;
        #pragma unroll
        for (int j = 0; j < 4; ++j)
            ra[j] = (aoff[j] >= 0) ? __ldg(&x[xb[j] + abase + aoff[j]]) : 0.f;
        rb = *(const float4*)&g_wt[lk * 512 + n0 + (lm << 2)];
        #pragma unroll
        for (int j = 0; j < 4; ++j) As[0][lk][lm + 32 * j] = ra[j];
        *(float4*)&Bs[0][lk][lm << 2] = rb;
    }
    __syncthreads();

    for (int kk = 0; kk < 1728; ++kk) {
        const int cb = kk & 1;
        const int nb = cb ^ 1;
        const bool more = (kk + 1 < 1728);

        // ---- prefetch next slice into registers ----
        if (more) {
            int kn = kk + 1;
            if ((kn & 63) == 0) {
                int tap = kn >> 6;
                int dt  = tap / 9 - 1;
                int rm  = tap - (tap / 9) * 9;
                int dh  = rm / 3 - 1;
                int dw  = rm - (rm / 3) * 3 - 1;
                #pragma unroll
                for (int j = 0; j < 4; ++j) {
                    int t = (pk[j] & 255) + dt;
                    int h = ((pk[j] >> 8) & 255) + dh;
                    int w = ((pk[j] >> 16) & 255) + dw;
                    bool ok = (unsigned)t < 16u && (unsigned)h < 15u && (unsigned)w < 20u;
                    aoff[j] = ok ? ((t * 15 + h) * 20 + w) : -1;
                }
            }
            int ci    = ((kn & 63) << 3) + lk;
            int abase = ci * THW;
            #pragma unroll
            for (int j = 0; j < 4; ++j)
                ra[j] = (aoff[j] >= 0) ? __ldg(&x[xb[j] + abase + aoff[j]]) : 0.f;
            rb = *(const float4*)&g_wt[((kn << 3) + lk) * 512 + n0 + (lm << 2)];
        }

        // ---- compute current slice (packed fp32x2 FMA) ----
        #pragma unroll
        for (int k = 0; k < 8; ++k) {
            float4 a0 = *(const float4*)&As[cb][k][ty << 2];
            float4 a1 = *(const float4*)&As[cb][k][64 + (ty << 2)];
            float4 b0 = *(const float4*)&Bs[cb][k][tx << 2];
            float4 b1 = *(const float4*)&Bs[cb][k][64 + (tx << 2)];
            unsigned long long bp0 = pack2(b0.x, b0.y);
            unsigned long long bp1 = pack2(b0.z, b0.w);
            unsigned long long bp2 = pack2(b1.x, b1.y);
            unsigned long long bp3 = pack2(b1.z, b1.w);
            float av[8] = {a0.x, a0.y, a0.z, a0.w, a1.x, a1.y, a1.z, a1.w};
            #pragma unroll
            for (int i = 0; i < 8; ++i) {
                unsigned long long ad = dup2(av[i]);
                fma2(acc[i][0], ad, bp0);
                fma2(acc[i][1], ad, bp1);
                fma2(acc[i][2], ad, bp2);
                fma2(acc[i][3], ad, bp3);
            }
        }

        // ---- Kahan merge every 8 slices ----
        if ((kk & 7) == 7) {
            #pragma unroll
            for (int i = 0; i < 8; ++i)
                #pragma unroll
                for (int p = 0; p < 4; ++p) {
                    unsigned long long y = add2(acc[i][p], neg2(cmp[i][p]));
                    unsigned long long t = add2(oac[i][p], y);
                    cmp[i][p] = add2(add2(t, neg2(oac[i][p])), neg2(y));
                    oac[i][p] = t;
                    acc[i][p] = 0ull;
                }
        }

        // ---- commit prefetched slice ----
        if (more) {
            #pragma unroll
            for (int j = 0; j < 4; ++j) As[nb][lk][lm + 32 * j] = ra[j];
            *(float4*)&Bs[nb][lk][lm << 2] = rb;
        }
        __syncthreads();
    }

    // ---- epilogue: add compensation, bias + relu, store [m][n] ----
    float4 bv0 = *(const float4*)&bias[n0 + (tx << 2)];
    float4 bv1 = *(const float4*)&bias[n0 + 64 + (tx << 2)];
    #pragma unroll
    for (int mi = 0; mi < 8; ++mi) {
        int ml = (mi < 4) ? ((ty << 2) + mi) : (64 + (ty << 2) + mi - 4);
        float v[8];
        #pragma unroll
        for (int p = 0; p < 4; ++p) {
            unsigned long long f = add2(oac[mi][p], cmp[mi][p]);
            unpack2(f, v[2 * p], v[2 * p + 1]);
        }
        float4 o0 = make_float4(fmaxf(v[0] + bv0.x, 0.f), fmaxf(v[1] + bv0.y, 0.f),
                                fmaxf(v[2] + bv0.z, 0.f), fmaxf(v[3] + bv0.w, 0.f));
        float4 o1 = make_float4(fmaxf(v[4] + bv1.x, 0.f), fmaxf(v[5] + bv1.y, 0.f),
                                fmaxf(v[6] + bv1.z, 0.f), fmaxf(v[7] + bv1.w, 0.f));
        float* dst = &g_rpn[(m0 + ml) * 512 + n0];
        *(float4*)&dst[tx << 2]        = o0;
        *(float4*)&dst[64 + (tx << 2)] = o1;
    }
}

// ---------------- kernel: 1x1x1 heads (cls + bbox fused GEMM, Kahan) -------
// M=38400 (grid.x=300), N=144 (grid.y=3, BN=48), K=512 (BK=16 chunks, Kahan merge)
__global__ __launch_bounds__(256) void k_head(const float* __restrict__ bc,
                                              const float* __restrict__ bb,
                                              float* __restrict__ out_bbox) {
    __shared__ float As[16][132];
    __shared__ float Bs[16][48];
    const int tid = threadIdx.x;
    const int m0  = blockIdx.x * 128;
    const int n0  = blockIdx.y * 48;
    const int tx  = tid & 15;
    const int ty  = tid >> 4;
    const int lm  = tid >> 1;
    const int lkq = (tid & 1) << 2;

    float oac[8][3], cmp[8][3];
    #pragma unroll
    for (int i = 0; i < 8; ++i)
        #pragma unroll
        for (int c = 0; c < 3; ++c) { oac[i][c] = 0.f; cmp[i][c] = 0.f; }

    for (int kk = 0; kk < 32; ++kk) {
        float4 a0 = *(const float4*)&g_rpn[(m0 + lm) * 512 + (kk << 4) + lkq];
        float4 a1 = *(const float4*)&g_rpn[(m0 + lm) * 512 + (kk << 4) + lkq + 8];
        float4 bw = make_float4(0.f, 0.f, 0.f, 0.f);
        int bk = 0, bn = 0;
        if (tid < 192) {
            bk = tid / 12;
            bn = (tid - bk * 12) << 2;
            bw = *(const float4*)&g_whead[((kk << 4) + bk) * 144 + n0 + bn];
        }
        __syncthreads();
        As[lkq + 0][lm] = a0.x;  As[lkq + 1][lm] = a0.y;
        As[lkq + 2][lm] = a0.z;  As[lkq + 3][lm] = a0.w;
        As[lkq + 8][lm] = a1.x;  As[lkq + 9][lm] = a1.y;
        As[lkq + 10][lm] = a1.z; As[lkq + 11][lm] = a1.w;
        if (tid < 192) *(float4*)&Bs[bk][bn] = bw;
        __syncthreads();

        float inn[8][3];
        #pragma unroll
        for (int i = 0; i < 8; ++i)
            #pragma unroll
            for (int c = 0; c < 3; ++c) inn[i][c] = 0.f;
        #pragma unroll
        for (int k = 0; k < 16; ++k) {
            float4 av0 = *(const float4*)&As[k][ty << 3];
            float4 av1 = *(const float4*)&As[k][(ty << 3) + 4];
            float b0 = Bs[k][tx * 3], b1 = Bs[k][tx * 3 + 1], b2 = Bs[k][tx * 3 + 2];
            float am[8] = {av0.x, av0.y, av0.z, av0.w, av1.x, av1.y, av1.z, av1.w};
            #pragma unroll
            for (int i = 0; i < 8; ++i) {
                inn[i][0] += am[i] * b0;
                inn[i][1] += am[i] * b1;
                inn[i][2] += am[i] * b2;
            }
        }
        // Kahan merge chunk
        #pragma unroll
        for (int i = 0; i < 8; ++i)
            #pragma unroll
            for (int c = 0; c < 3; ++c) {
                float y = inn[i][c] - cmp[i][c];
                float t = oac[i][c] + y;
                cmp[i][c] = (t - oac[i][c]) - y;
                oac[i][c] = t;
            }
    }

    #pragma unroll
    for (int i = 0; i < 8; ++i) {
        int m   = m0 + (ty << 3) + i;
        int b   = m / THW;
        int pos = m - b * THW;
        #pragma unroll
        for (int c = 0; c < 3; ++c) {
            int n = n0 + tx * 3 + c;
            float v = oac[i][c] + cmp[i][c];
            if (n < 36) {
                g_cls[(b * 36 + n) * THW + pos] = v + bc[n];
            } else {
                int ch = n - 36;
                out_bbox[(b * 108 + ch) * THW + pos] = v + bb[ch];
            }
        }
    }
}

// ---------------- kernel: softmax probs + score keys -----------------------
__global__ void k_prob(float* __restrict__ out_prob) {
    int i = blockIdx.x * 256 + threadIdx.x;
    if (i >= 8 * NPROP) return;
    int b   = i / NPROP;
    int r   = i - b * NPROP;
    int pos = r / 18;
    int a   = r - pos * 18;
    float s0 = g_cls[(b * 36 + a) * THW + pos];
    float s1 = g_cls[(b * 36 + 18 + a) * THW + pos];
    float mx = fmaxf(s0, s1);
    float e0 = expf(s0 - mx), e1 = expf(s1 - mx);
    float s  = e0 + e1;
    float p0 = e0 / s, p1 = e1 / s;
    out_prob[(b * 36 + a) * THW + pos]      = p0;
    out_prob[(b * 36 + 18 + a) * THW + pos] = p1;
    g_okey[b * NPROP + r] = okey(p1);
}

// ---------------- kernel: bbox decode + clip -------------------------------
__global__ void k_prop(const float* __restrict__ anchors,
                       const float* __restrict__ im_info,
                       const float* __restrict__ bbox) {
    int i = blockIdx.x * 256 + threadIdx.x;
    if (i >= 8 * NPROP) return;
    int b   = i / NPROP;
    int r   = i - b * NPROP;
    int pos = r / 18;
    int a   = r - pos * 18;
    const float* an = &anchors[r * 6];
    float aw = an[3] - an[0] + 1.f;
    float ah = an[4] - an[1] + 1.f;
    float al = an[5] - an[2] + 1.f;
    float cx = an[0] + 0.5f * aw;
    float cy = an[1] + 0.5f * ah;
    float ct = an[2] + 0.5f * al;
    const float* dp = &bbox[(b * 108 + a * 6) * THW + pos];
    float d0 = dp[0], d1 = dp[THW], d2 = dp[2 * THW];
    float d3 = dp[3 * THW], d4 = dp[4 * THW], d5 = dp[5 * THW];
    float pcx = d0 * aw + cx, pcy = d1 * ah + cy, pct = d2 * al + ct;
    float pw = expf(d3) * aw, ph = expf(d4) * ah, pl = expf(d5) * al;
    float hx = im_info[b * 3 + 1] - 1.f;
    float hy = im_info[b * 3 + 0] - 1.f;
    float htt = 15.f;
    float* o = &g_props[(b * NPROP + r) * 6];
    o[0] = fminf(fmaxf(pcx - 0.5f * pw, 0.f), hx);
    o[1] = fminf(fmaxf(pcy - 0.5f * ph, 0.f), hy);
    o[2] = fminf(fmaxf(pct - 0.5f * pl, 0.f), htt);
    o[3] = fminf(fmaxf(pcx + 0.5f * pw, 0.f), hx);
    o[4] = fminf(fmaxf(pcy + 0.5f * ph, 0.f), hy);
    o[5] = fminf(fmaxf(pct + 0.5f * pl, 0.f), htt);
}

// ---------------- kernel: per-batch top-300 (jax.lax.top_k semantics) ------
__global__ __launch_bounds__(1024) void k_topk(float* __restrict__ out) {
    const int b   = blockIdx.x;
    const int tid = threadIdx.x;
    const unsigned* key = g_okey + b * NPROP;

    __shared__ int s_cnt, n_gt, n_eq;
    __shared__ unsigned s_lo, s_hi;
    __shared__ int win[300];
    __shared__ int eq_buf[4096];
    __shared__ unsigned long long skey[512];

    if (tid == 0) { s_lo = 0u; s_hi = 0xFFFFFFFFu; }
    __syncthreads();

    for (int it = 0; it < 32; ++it) {
        unsigned lo = s_lo, hi = s_hi;
        unsigned mid = lo + (unsigned)((((unsigned long long)hi - lo + 1ull)) >> 1);
        if (tid == 0) s_cnt = 0;
        __syncthreads();
        int c = 0;
        for (int i = tid; i < NPROP; i += 1024) c += (key[i] >= mid);
        #pragma unroll
        for (int o = 16; o > 0; o >>= 1) c += __shfl_down_sync(0xffffffffu, c, o);
        if ((tid & 31) == 0) atomicAdd(&s_cnt, c);
        __syncthreads();
        if (tid == 0) {
            if (s_cnt >= 300) s_lo = mid; else s_hi = mid - 1u;
        }
        __syncthreads();
    }
    const unsigned V = s_lo;

    if (tid == 0) { n_gt = 0; n_eq = 0; }
    __syncthreads();
    for (int i = tid; i < NPROP; i += 1024) {
        unsigned u = key[i];
        if (u > V) {
            int p = atomicAdd(&n_gt, 1);
            win[p] = i;
        } else if (u == V) {
            int p = atomicAdd(&n_eq, 1);
            if (p < 4096) eq_buf[p] = i;
        }
    }
    __syncthreads();

    const int need = 300 - n_gt;
    const int ne = (n_eq < 4096) ? n_eq : 4096;
    for (int j = tid; j < ne; j += 1024) {
        int v = eq_buf[j];
        int rk = 0;
        for (int q = 0; q < ne; ++q) rk += (eq_buf[q] < v);
        if (rk < need) win[n_gt + rk] = v;
    }
    __syncthreads();

    for (int i = tid; i < 512; i += 1024) {
        if (i < 300) {
            int idx = win[i];
            skey[i] = ((unsigned long long)key[idx] << 32) | (unsigned)(~(unsigned)idx);
        } else {
            skey[i] = 0ull;
        }
    }
    __syncthreads();
    for (int ks = 2; ks <= 512; ks <<= 1) {
        for (int js = ks >> 1; js > 0; js >>= 1) {
            if (tid < 512) {
                int i = tid, ixj = i ^ js;
                if (ixj > i) {
                    unsigned long long A = skey[i], B2 = skey[ixj];
                    bool up = (i & ks) == 0;
                    bool sw = up ? (A < B2) : (A > B2);
                    if (sw) { skey[i] = B2; skey[ixj] = A; }
                }
            }
            __syncthreads();
        }
    }

    for (int r = tid; r < 300; r += 1024) {
        unsigned long long kv = skey[r];
        int idx = (int)(~(unsigned)kv);
        const float* p = &g_props[(b * NPROP + idx) * 6];
        float* o = out + (b * 300 + r) * 7;
        o[0] = (float)b;
        o[1] = p[0]; o[2] = p[1]; o[3] = p[2];
        o[4] = p[3]; o[5] = p[4]; o[6] = p[5];
    }
}

// ---------------- launch ----------------
extern "C" void kernel_launch(void* const* d_in, const int* in_sizes, int n_in,
                              void* d_out, int out_size) {
    const float* base_feat = (const float*)d_in[0];
    const float* im_info   = (const float*)d_in[1];
    const float* W_conv    = (const float*)d_in[2];
    const float* b_conv    = (const float*)d_in[3];
    const float* W_cls     = (const float*)d_in[4];
    const float* b_cls     = (const float*)d_in[5];
    const float* W_bbox    = (const float*)d_in[6];
    const float* b_bbox    = (const float*)d_in[7];
    const float* anchors   = (const float*)d_in[8];
    float* out = (float*)d_out;

    k_wt<<<(KTOT * 512 + 255) / 256, 256>>>(W_conv);
    k_whead<<<(512 * 144 + 255) / 256, 256>>>(W_cls, W_bbox);
    k_conv<<<dim3(300, 4), 256>>>(base_feat, b_conv);
    k_head<<<dim3(300, 3), 256>>>(b_cls, b_bbox, out + OUT_BBOX);
    k_prob<<<(8 * NPROP + 255) / 256, 256>>>(out + OUT_PROB);
    k_prop<<<(8 * NPROP + 255) / 256, 256>>>(anchors, im_info, out + OUT_BBOX);
    k_topk<<<8, 1024>>>(out);
}

// round 9
// speedup vs baseline: 1.4991x; 1.4991x over previous
#include <cuda_runtime.h>
#include <cuda_bf16.h>
#include <cstdint>

#define THW   4800
#define NPROP 86400
#define OUT_PROB 16800
#define OUT_BBOX (16800 + 1382400)

__device__ __nv_bfloat16 g_xs[3][8 * THW * 512];
__device__ __nv_bfloat16 g_ws[3][27 * 8 * 512 * 64];
__device__ float    g_rpn[8 * THW * 512];
__device__ float    g_whead[512 * 144];
__device__ float    g_cls[8 * 36 * THW];
__device__ unsigned g_okey[8 * NPROP];
__device__ float    g_props[8 * NPROP * 6];

__device__ __forceinline__ uint32_t smem_u32(const void* p) {
    uint32_t a;
    asm("{ .reg .u64 t; cvta.to.shared.u64 t, %1; cvt.u32.u64 %0, t; }" : "=r"(a) : "l"(p));
    return a;
}
__device__ __forceinline__ unsigned okey(float f) {
    unsigned u = __float_as_uint(f);
    return (u & 0x80000000u) ? ~u : (u | 0x80000000u);
}
#define SW128(o) ((o) ^ (((o) >> 3) & 0x70))

__device__ __forceinline__ void ldmx4(uint32_t& r0, uint32_t& r1, uint32_t& r2, uint32_t& r3, uint32_t ad) {
    asm volatile("ldmatrix.sync.aligned.m8n8.x4.shared.b16 {%0,%1,%2,%3}, [%4];"
                 : "=r"(r0), "=r"(r1), "=r"(r2), "=r"(r3) : "r"(ad));
}
__device__ __forceinline__ void mma16816(float* c, const uint32_t* a, uint32_t b0, uint32_t b1) {
    asm volatile("mma.sync.aligned.m16n8k16.row.col.f32.bf16.bf16.f32 "
                 "{%0,%1,%2,%3}, {%4,%5,%6,%7}, {%8,%9}, {%0,%1,%2,%3};"
                 : "+f"(c[0]), "+f"(c[1]), "+f"(c[2]), "+f"(c[3])
                 : "r"(a[0]), "r"(a[1]), "r"(a[2]), "r"(a[3]), "r"(b0), "r"(b1));
}
__device__ __forceinline__ void cpasync(uint32_t dst, const void* src, uint32_t sz) {
    asm volatile("cp.async.cg.shared.global [%0], [%1], 16, %2;" :: "r"(dst), "l"(src), "r"(sz) : "memory");
}
__device__ __forceinline__ void split3(float v, __nv_bfloat16& h0, __nv_bfloat16& h1, __nv_bfloat16& h2) {
    h0 = __float2bfloat16(v);
    float r1 = v - __bfloat162float(h0);
    h1 = __float2bfloat16(r1);
    h2 = __float2bfloat16(r1 - __bfloat162float(h1));
}

__global__ void k_split_x(const float* __restrict__ x) {
    __shared__ float tile[32][33];
    int b = blockIdx.z, p0 = blockIdx.x * 32, c0 = blockIdx.y * 32;
    int tx = threadIdx.x & 31, ty = threadIdx.x >> 5;
    #pragma unroll
    for (int j = 0; j < 4; ++j)
        tile[ty + 8 * j][tx] = x[(b * 512 + c0 + ty + 8 * j) * THW + p0 + tx];
    __syncthreads();
    #pragma unroll
    for (int j = 0; j < 4; ++j) {
        __nv_bfloat16 h0, h1, h2;
        split3(tile[tx][ty + 8 * j], h0, h1, h2);
        int o = (b * THW + p0 + ty + 8 * j) * 512 + c0 + tx;
        g_xs[0][o] = h0; g_xs[1][o] = h1; g_xs[2][o] = h2;
    }
}

__global__ void k_split_w(const float* __restrict__ w) {
    int i = blockIdx.x * 256 + threadIdx.x;
    if (i >= 512 * 512) return;
    int co = i >> 9, ci = i & 511;
    #pragma unroll 1
    for (int tap = 0; tap < 27; ++tap) {
        __nv_bfloat16 h0, h1, h2;
        split3(w[i * 27 + tap], h0, h1, h2);
        int o = ((tap * 8 + (ci >> 6)) * 512 + co) * 64 + (ci & 63);
        g_ws[0][o] = h0; g_ws[1][o] = h1; g_ws[2][o] = h2;
    }
}

__global__ void k_whead(const float* __restrict__ wc, const float* __restrict__ wb) {
    int i = blockIdx.x * 256 + threadIdx.x;
    if (i >= 512 * 144) return;
    int k = i / 144, n = i - k * 144;
    g_whead[i] = (n < 36) ? __ldg(&wc[n * 512 + k]) : __ldg(&wb[(n - 36) * 512 + k]);
}

// conv: mma.sync bf16 3-split. grid(300,4), 256 thr, 216 stages (27 tap x 8 cihi).
#define SMEM_CONV (2 * 98304 + 1024)
__global__ __launch_bounds__(256, 1) void k_conv_mma(const float* __restrict__ bias) {
    extern __shared__ __align__(1024) char smem[];
    const int tid = threadIdx.x, wid = tid >> 5, lane = tid & 31;
    const int m0 = blockIdx.x * 128, n0 = blockIdx.y * 128;
    const uint32_t sb = smem_u32(smem);
    int* s_pk = (int*)(smem + 196608);

    if (tid < 128) {
        int m = m0 + tid, b = m / THW, pos = m - b * THW;
        int t = pos / 300, r = pos - t * 300, h = r / 20, w = r - h * 20;
        s_pk[tid] = t | (h << 8) | (w << 16) | (b << 24);
    }
    __syncthreads();

    const int m_off = (wid & 1) * 64, n_off = (wid >> 1) * 32;
    const int a_rl = (lane & 7) + 8 * ((lane >> 3) & 1), a_ko = 8 * (lane >> 4);
    const int b_rl = (lane & 7) + 8 * (lane >> 4),       b_ko = 8 * ((lane >> 3) & 1);

    float acc[4][4][4], oac[4][4][4];
    #pragma unroll
    for (int mi = 0; mi < 4; ++mi)
        #pragma unroll
        for (int ni = 0; ni < 4; ++ni)
            #pragma unroll
            for (int r = 0; r < 4; ++r) { acc[mi][ni][r] = 0.f; oac[mi][ni][r] = 0.f; }

    auto issue = [&](int stage) {
        int tap = stage >> 3, cihi = stage & 7;
        int dt = tap / 9 - 1, rm = tap % 9, dh = rm / 3 - 1, dw = rm % 3 - 1;
        uint32_t bufb = sb + (stage & 1) * 98304;
        #pragma unroll
        for (int i = 0; i < 12; ++i) {
            int idx = i * 256 + tid, s = idx >> 10, rem = idx & 1023, row = rem >> 3, u = rem & 7;
            int pk = s_pk[row];
            int t = (pk & 255) + dt, h = ((pk >> 8) & 255) + dh, w = ((pk >> 16) & 255) + dw;
            const __nv_bfloat16* src = &g_xs[s][0];
            uint32_t sz = 0;
            if ((unsigned)t < 16u && (unsigned)h < 15u && (unsigned)w < 20u) {
                src = &g_xs[s][(((pk >> 24) & 255) * THW + (t * 15 + h) * 20 + w) * 512 + cihi * 64 + u * 8];
                sz = 16;
            }
            cpasync(bufb + s * 16384 + SW128(row * 128 + u * 16), src, sz);
        }
        #pragma unroll
        for (int i = 0; i < 12; ++i) {
            int idx = i * 256 + tid, s = idx >> 10, rem = idx & 1023, row = rem >> 3, u = rem & 7;
            cpasync(bufb + 49152 + s * 16384 + SW128(row * 128 + u * 16),
                    &g_ws[s][((tap * 8 + cihi) * 512 + n0 + row) * 64 + u * 8], 16);
        }
        asm volatile("cp.async.commit_group;" ::: "memory");
    };

    issue(0);
    for (int stage = 0; stage < 216; ++stage) {
        if (stage + 1 < 216) {
            issue(stage + 1);
            asm volatile("cp.async.wait_group 1;" ::: "memory");
        } else {
            asm volatile("cp.async.wait_group 0;" ::: "memory");
        }
        __syncthreads();
        uint32_t bufb = sb + (stage & 1) * 98304;

        #pragma unroll
        for (int k16 = 0; k16 < 4; ++k16) {
            const int kb = k16 * 16;
            uint32_t bfr[3][8];
            #pragma unroll
            for (int s = 0; s < 3; ++s) {
                uint32_t bbase = bufb + 49152 + s * 16384;
                #pragma unroll
                for (int p = 0; p < 2; ++p) {
                    uint32_t ad = bbase + SW128((n_off + p * 16 + b_rl) * 128 + (kb + b_ko) * 2);
                    ldmx4(bfr[s][4 * p], bfr[s][4 * p + 1], bfr[s][4 * p + 2], bfr[s][4 * p + 3], ad);
                }
            }
            #pragma unroll
            for (int sa = 0; sa < 3; ++sa) {
                uint32_t af[4][4];
                uint32_t abase = bufb + sa * 16384;
                #pragma unroll
                for (int mi = 0; mi < 4; ++mi) {
                    uint32_t ad = abase + SW128((m_off + mi * 16 + a_rl) * 128 + (kb + a_ko) * 2);
                    ldmx4(af[mi][0], af[mi][1], af[mi][2], af[mi][3], ad);
                }
                const int nb = (sa == 0) ? 3 : ((sa == 1) ? 2 : 1);  // products: 00,01,02,10,11,20
                #pragma unroll
                for (int sbv = 0; sbv < 3; ++sbv) {
                    if (sbv < nb) {
                        #pragma unroll
                        for (int mi = 0; mi < 4; ++mi)
                            #pragma unroll
                            for (int ni = 0; ni < 4; ++ni)
                                mma16816(acc[mi][ni], af[mi], bfr[sbv][2 * ni], bfr[sbv][2 * ni + 1]);
                    }
                }
            }
        }
        __syncthreads();

        if ((stage & 7) == 7) {
            #pragma unroll
            for (int mi = 0; mi < 4; ++mi)
                #pragma unroll
                for (int ni = 0; ni < 4; ++ni)
                    #pragma unroll
                    for (int r = 0; r < 4; ++r) {
                        oac[mi][ni][r] += acc[mi][ni][r];
                        acc[mi][ni][r] = 0.f;
                    }
        }
    }

    #pragma unroll
    for (int mi = 0; mi < 4; ++mi)
        #pragma unroll
        for (int ni = 0; ni < 4; ++ni)
            #pragma unroll
            for (int r = 0; r < 4; ++r) {
                int m  = m0 + m_off + mi * 16 + (lane >> 2) + 8 * (r >> 1);
                int co = n0 + n_off + ni * 8 + ((lane & 3) << 1) + (r & 1);
                g_rpn[m * 512 + co] = fmaxf(oac[mi][ni][r] + __ldg(&bias[co]), 0.f);
            }
}

__global__ __launch_bounds__(256) void k_head(const float* __restrict__ bc,
                                              const float* __restrict__ bb,
                                              float* __restrict__ out_bbox) {
    __shared__ float As[16][132];
    __shared__ float Bs[16][48];
    const int tid = threadIdx.x, m0 = blockIdx.x * 128, n0 = blockIdx.y * 48;
    const int tx = tid & 15, ty = tid >> 4, lm = tid >> 1, lkq = (tid & 1) << 2;
    float oac[8][3], cmp[8][3];
    #pragma unroll
    for (int i = 0; i < 8; ++i)
        #pragma unroll
        for (int c = 0; c < 3; ++c) { oac[i][c] = 0.f; cmp[i][c] = 0.f; }
    for (int kk = 0; kk < 32; ++kk) {
        float4 a0 = *(const float4*)&g_rpn[(m0 + lm) * 512 + (kk << 4) + lkq];
        float4 a1 = *(const float4*)&g_rpn[(m0 + lm) * 512 + (kk << 4) + lkq + 8];
        float4 bw = make_float4(0.f, 0.f, 0.f, 0.f);
        int bk = 0, bn = 0;
        if (tid < 192) {
            bk = tid / 12; bn = (tid - bk * 12) << 2;
            bw = *(const float4*)&g_whead[((kk << 4) + bk) * 144 + n0 + bn];
        }
        __syncthreads();
        As[lkq + 0][lm] = a0.x;  As[lkq + 1][lm] = a0.y;  As[lkq + 2][lm] = a0.z;  As[lkq + 3][lm] = a0.w;
        As[lkq + 8][lm] = a1.x;  As[lkq + 9][lm] = a1.y;  As[lkq + 10][lm] = a1.z; As[lkq + 11][lm] = a1.w;
        if (tid < 192) *(float4*)&Bs[bk][bn] = bw;
        __syncthreads();
        float inn[8][3];
        #pragma unroll
        for (int i = 0; i < 8; ++i)
            #pragma unroll
            for (int c = 0; c < 3; ++c) inn[i][c] = 0.f;
        #pragma unroll
        for (int k = 0; k < 16; ++k) {
            float4 av0 = *(const float4*)&As[k][ty << 3];
            float4 av1 = *(const float4*)&As[k][(ty << 3) + 4];
            float b0 = Bs[k][tx * 3], b1 = Bs[k][tx * 3 + 1], b2 = Bs[k][tx * 3 + 2];
            float am[8] = {av0.x, av0.y, av0.z, av0.w, av1.x, av1.y, av1.z, av1.w};
            #pragma unroll
            for (int i = 0; i < 8; ++i) {
                inn[i][0] += am[i] * b0; inn[i][1] += am[i] * b1; inn[i][2] += am[i] * b2;
            }
        }
        #pragma unroll
        for (int i = 0; i < 8; ++i)
            #pragma unroll
            for (int c = 0; c < 3; ++c) {
                float y = inn[i][c] - cmp[i][c], t = oac[i][c] + y;
                cmp[i][c] = (t - oac[i][c]) - y; oac[i][c] = t;
            }
    }
    #pragma unroll
    for (int i = 0; i < 8; ++i) {
        int m = m0 + (ty << 3) + i, b = m / THW, pos = m - b * THW;
        #pragma unroll
        for (int c = 0; c < 3; ++c) {
            int n = n0 + tx * 3 + c;
            float v = oac[i][c] + cmp[i][c];
            if (n < 36) g_cls[(b * 36 + n) * THW + pos] = v + bc[n];
            else        out_bbox[(b * 108 + (n - 36)) * THW + pos] = v + bb[n - 36];
        }
    }
}

__global__ void k_prob(float* __restrict__ out_prob) {
    int i = blockIdx.x * 256 + threadIdx.x;
    if (i >= 8 * NPROP) return;
    int b = i / NPROP, r = i - b * NPROP, pos = r / 18, a = r - pos * 18;
    float s0 = g_cls[(b * 36 + a) * THW + pos];
    float s1 = g_cls[(b * 36 + 18 + a) * THW + pos];
    float mx = fmaxf(s0, s1);
    float e0 = expf(s0 - mx), e1 = expf(s1 - mx), s = e0 + e1;
    out_prob[(b * 36 + a) * THW + pos]      = e0 / s;
    out_prob[(b * 36 + 18 + a) * THW + pos] = e1 / s;
    g_okey[b * NPROP + r] = okey(e1 / s);
}

__global__ void k_prop(const float* __restrict__ anchors, const float* __restrict__ im_info,
                       const float* __restrict__ bbox) {
    int i = blockIdx.x * 256 + threadIdx.x;
    if (i >= 8 * NPROP) return;
    int b = i / NPROP, r = i - b * NPROP, pos = r / 18, a = r - pos * 18;
    const float* an = &anchors[r * 6];
    float aw = an[3] - an[0] + 1.f, ah = an[4] - an[1] + 1.f, al = an[5] - an[2] + 1.f;
    float cx = an[0] + 0.5f * aw, cy = an[1] + 0.5f * ah, ct = an[2] + 0.5f * al;
    const float* dp = &bbox[(b * 108 + a * 6) * THW + pos];
    float pcx = dp[0] * aw + cx, pcy = dp[THW] * ah + cy, pct = dp[2 * THW] * al + ct;
    float pw = expf(dp[3 * THW]) * aw, ph = expf(dp[4 * THW]) * ah, pl = expf(dp[5 * THW]) * al;
    float hx = im_info[b * 3 + 1] - 1.f, hy = im_info[b * 3 + 0] - 1.f;
    float* o = &g_props[(b * NPROP + r) * 6];
    o[0] = fminf(fmaxf(pcx - 0.5f * pw, 0.f), hx);
    o[1] = fminf(fmaxf(pcy - 0.5f * ph, 0.f), hy);
    o[2] = fminf(fmaxf(pct - 0.5f * pl, 0.f), 15.f);
    o[3] = fminf(fmaxf(pcx + 0.5f * pw, 0.f), hx);
    o[4] = fminf(fmaxf(pcy + 0.5f * ph, 0.f), hy);
    o[5] = fminf(fmaxf(pct + 0.5f * pl, 0.f), 15.f);
}

__global__ __launch_bounds__(1024) void k_topk(float* __restrict__ out) {
    const int b = blockIdx.x, tid = threadIdx.x;
    const unsigned* key = g_okey + b * NPROP;
    __shared__ int s_cnt, n_gt, n_eq;
    __shared__ unsigned s_lo, s_hi;
    __shared__ int win[300];
    __shared__ int eq_buf[4096];
    __shared__ unsigned long long skey[512];
    if (tid == 0) { s_lo = 0u; s_hi = 0xFFFFFFFFu; }
    __syncthreads();
    for (int it = 0; it < 32; ++it) {
        unsigned lo = s_lo, hi = s_hi;
        unsigned mid = lo + (unsigned)((((unsigned long long)hi - lo + 1ull)) >> 1);
        if (tid == 0) s_cnt = 0;
        __syncthreads();
        int c = 0;
        for (int i = tid; i < NPROP; i += 1024) c += (key[i] >= mid);
        #pragma unroll
        for (int o = 16; o > 0; o >>= 1) c += __shfl_down_sync(0xffffffffu, c, o);
        if ((tid & 31) == 0) atomicAdd(&s_cnt, c);
        __syncthreads();
        if (tid == 0) { if (s_cnt >= 300) s_lo = mid; else s_hi = mid - 1u; }
        __syncthreads();
    }
    const unsigned V = s_lo;
    if (tid == 0) { n_gt = 0; n_eq = 0; }
    __syncthreads();
    for (int i = tid; i < NPROP; i += 1024) {
        unsigned u = key[i];
        if (u > V)       { int p = atomicAdd(&n_gt, 1); win[p] = i; }
        else if (u == V) { int p = atomicAdd(&n_eq, 1); if (p < 4096) eq_buf[p] = i; }
    }
    __syncthreads();
    const int need = 300 - n_gt;
    const int ne = (n_eq < 4096) ? n_eq : 4096;
    for (int j = tid; j < ne; j += 1024) {
        int v = eq_buf[j], rk = 0;
        for (int q = 0; q < ne; ++q) rk += (eq_buf[q] < v);
        if (rk < need) win[n_gt + rk] = v;
    }
    __syncthreads();
    for (int i = tid; i < 512; i += 1024) {
        if (i < 300) {
            int idx = win[i];
            skey[i] = ((unsigned long long)key[idx] << 32) | (unsigned)(~(unsigned)idx);
        } else skey[i] = 0ull;
    }
    __syncthreads();
    for (int ks = 2; ks <= 512; ks <<= 1)
        for (int js = ks >> 1; js > 0; js >>= 1) {
            if (tid < 512) {
                int i = tid, ixj = i ^ js;
                if (ixj > i) {
                    unsigned long long A = skey[i], B2 = skey[ixj];
                    bool up = (i & ks) == 0;
                    if (up ? (A < B2) : (A > B2)) { skey[i] = B2; skey[ixj] = A; }
                }
            }
            __syncthreads();
        }
    for (int r = tid; r < 300; r += 1024) {
        int idx = (int)(~(unsigned)skey[r]);
        const float* p = &g_props[(b * NPROP + idx) * 6];
        float* o = out + (b * 300 + r) * 7;
        o[0] = (float)b;
        o[1] = p[0]; o[2] = p[1]; o[3] = p[2]; o[4] = p[3]; o[5] = p[4]; o[6] = p[5];
    }
}

extern "C" void kernel_launch(void* const* d_in, const int* in_sizes, int n_in,
                              void* d_out, int out_size) {
    const float* base_feat = (const float*)d_in[0];
    const float* im_info   = (const float*)d_in[1];
    const float* W_conv    = (const float*)d_in[2];
    const float* b_conv    = (const float*)d_in[3];
    const float* W_cls     = (const float*)d_in[4];
    const float* b_cls     = (const float*)d_in[5];
    const float* W_bbox    = (const float*)d_in[6];
    const float* b_bbox    = (const float*)d_in[7];
    const float* anchors   = (const float*)d_in[8];
    float* out = (float*)d_out;

    cudaFuncSetAttribute(k_conv_mma, cudaFuncAttributeMaxDynamicSharedMemorySize, SMEM_CONV);
    k_split_x<<<dim3(150, 16, 8), 256>>>(base_feat);
    k_split_w<<<1024, 256>>>(W_conv);
    k_whead<<<288, 256>>>(W_cls, W_bbox);
    k_conv_mma<<<dim3(300, 4), 256, SMEM_CONV>>>(b_conv);
    k_head<<<dim3(300, 3), 256>>>(b_cls, b_bbox, out + OUT_BBOX);
    k_prob<<<2700, 256>>>(out + OUT_PROB);
    k_prop<<<2700, 256>>>(anchors, im_info, out + OUT_BBOX);
    k_topk<<<8, 1024>>>(out);
}

// round 13
// speedup vs baseline: 2.4910x; 1.6617x over previous
#include <cuda_runtime.h>
#include <cuda_fp16.h>
#include <cstdint>

#define THW   4800
#define NPROP 86400
#define OUT_PROB 16800
#define OUT_BBOX (16800 + 1382400)

__device__ __half  g_xs[2][8 * THW * 512];
__device__ __half  g_ws[2][27 * 8 * 512 * 64];
__device__ float    g_rpn[8 * THW * 512];
__device__ float    g_whead[512 * 144];
__device__ float    g_cls[8 * 36 * THW];
__device__ unsigned g_okey[8 * NPROP];
__device__ float    g_props[8 * NPROP * 6];

__device__ __forceinline__ uint32_t smem_u32(const void* p) {
    uint32_t a;
    asm("{ .reg .u64 t; cvta.to.shared.u64 t, %1; cvt.u32.u64 %0, t; }" : "=r"(a) : "l"(p));
    return a;
}
__device__ __forceinline__ unsigned okey(float f) {
    unsigned u = __float_as_uint(f);
    return (u & 0x80000000u) ? ~u : (u | 0x80000000u);
}
#define SW128(o) ((o) ^ (((o) >> 3) & 0x70))

__device__ __forceinline__ void ldmx4(uint32_t& r0, uint32_t& r1, uint32_t& r2, uint32_t& r3, uint32_t ad) {
    asm volatile("ldmatrix.sync.aligned.m8n8.x4.shared.b16 {%0,%1,%2,%3}, [%4];"
                 : "=r"(r0), "=r"(r1), "=r"(r2), "=r"(r3) : "r"(ad));
}
__device__ __forceinline__ void mma16816(float* c, const uint32_t* a, uint32_t b0, uint32_t b1) {
    asm volatile("mma.sync.aligned.m16n8k16.row.col.f32.f16.f16.f32 "
                 "{%0,%1,%2,%3}, {%4,%5,%6,%7}, {%8,%9}, {%0,%1,%2,%3};"
                 : "+f"(c[0]), "+f"(c[1]), "+f"(c[2]), "+f"(c[3])
                 : "r"(a[0]), "r"(a[1]), "r"(a[2]), "r"(a[3]), "r"(b0), "r"(b1));
}
__device__ __forceinline__ void cpasync(uint32_t dst, const void* src, uint32_t sz) {
    asm volatile("cp.async.cg.shared.global [%0], [%1], 16, %2;" :: "r"(dst), "l"(src), "r"(sz) : "memory");
}
// fp16 2-split: v = h0 + h1 * 2^-11  (h1 stored pre-scaled by 2^11)
__device__ __forceinline__ void split2(float v, __half& h0, __half& h1) {
    h0 = __float2half_rn(v);
    h1 = __float2half_rn((v - __half2float(h0)) * 2048.0f);
}

__global__ void k_split_x(const float* __restrict__ x) {
    __shared__ float tile[32][33];
    int b = blockIdx.z, p0 = blockIdx.x * 32, c0 = blockIdx.y * 32;
    int tx = threadIdx.x & 31, ty = threadIdx.x >> 5;
    #pragma unroll
    for (int j = 0; j < 4; ++j)
        tile[ty + 8 * j][tx] = x[(b * 512 + c0 + ty + 8 * j) * THW + p0 + tx];
    __syncthreads();
    #pragma unroll
    for (int j = 0; j < 4; ++j) {
        __half h0, h1;
        split2(tile[tx][ty + 8 * j], h0, h1);
        int o = (b * THW + p0 + ty + 8 * j) * 512 + c0 + tx;
        g_xs[0][o] = h0; g_xs[1][o] = h1;
    }
}

__global__ void k_split_w(const float* __restrict__ w) {
    int i = blockIdx.x * 256 + threadIdx.x;
    if (i >= 512 * 512) return;
    int co = i >> 9, ci = i & 511;
    #pragma unroll 1
    for (int tap = 0; tap < 27; ++tap) {
        __half h0, h1;
        split2(w[i * 27 + tap], h0, h1);
        int o = ((tap * 8 + (ci >> 6)) * 512 + co) * 64 + (ci & 63);
        g_ws[0][o] = h0; g_ws[1][o] = h1;
    }
}

__global__ void k_whead(const float* __restrict__ wc, const float* __restrict__ wb) {
    int i = blockIdx.x * 256 + threadIdx.x;
    if (i >= 512 * 144) return;
    int k = i / 144, n = i - k * 144;
    g_whead[i] = (n < 36) ? __ldg(&wc[n * 512 + k]) : __ldg(&wb[(n - 36) * 512 + k]);
}

// conv: mma.sync fp16 2-split (3 products), smem outer accumulator.
// grid(300,4), 256 thr, 216 stages. smem: 128KB staging + s_pk + 64KB oac.
#define SMEM_CONV (131072 + 512 + 65536)
__global__ __launch_bounds__(256, 1) void k_conv_mma(const float* __restrict__ bias) {
    extern __shared__ __align__(1024) char smem[];
    const int tid = threadIdx.x, wid = tid >> 5, lane = tid & 31;
    const int m0 = blockIdx.x * 128, n0 = blockIdx.y * 128;
    const uint32_t sb = smem_u32(smem);
    int*   s_pk  = (int*)(smem + 131072);
    float* s_oac = (float*)(smem + 131584);   // [64][256] thread-strided

    if (tid < 128) {
        int m = m0 + tid, b = m / THW, pos = m - b * THW;
        int t = pos / 300, r = pos - t * 300, h = r / 20, w = r - h * 20;
        s_pk[tid] = t | (h << 8) | (w << 16) | (b << 24);
    }
    #pragma unroll
    for (int i = 0; i < 64; ++i) s_oac[i * 256 + tid] = 0.f;
    __syncthreads();

    const int m_off = (wid & 1) * 64, n_off = (wid >> 1) * 32;
    const int a_rl = (lane & 7) + 8 * ((lane >> 3) & 1), a_ko = 8 * (lane >> 4);
    const int b_rl = (lane & 7) + 8 * (lane >> 4),       b_ko = 8 * ((lane >> 3) & 1);

    float accA[4][4][4], accB[4][4][4];
    #pragma unroll
    for (int mi = 0; mi < 4; ++mi)
        #pragma unroll
        for (int ni = 0; ni < 4; ++ni)
            #pragma unroll
            for (int r = 0; r < 4; ++r) { accA[mi][ni][r] = 0.f; accB[mi][ni][r] = 0.f; }

    auto issue = [&](int stage) {
        int tap = stage >> 3, cihi = stage & 7;
        int dt = tap / 9 - 1, rm = tap % 9, dh = rm / 3 - 1, dw = rm % 3 - 1;
        uint32_t bufb = sb + (stage & 1) * 65536;
        #pragma unroll
        for (int i = 0; i < 8; ++i) {                 // A: 2 splits x 1024 units
            int idx = i * 256 + tid, s = idx >> 10, rem = idx & 1023, row = rem >> 3, u = rem & 7;
            int pk = s_pk[row];
            int t = (pk & 255) + dt, h = ((pk >> 8) & 255) + dh, w = ((pk >> 16) & 255) + dw;
            const __half* src = &g_xs[s][0];
            uint32_t sz = 0;
            if ((unsigned)t < 16u && (unsigned)h < 15u && (unsigned)w < 20u) {
                src = &g_xs[s][(((pk >> 24) & 255) * THW + (t * 15 + h) * 20 + w) * 512 + cihi * 64 + u * 8];
                sz = 16;
            }
            cpasync(bufb + s * 16384 + SW128(row * 128 + u * 16), src, sz);
        }
        #pragma unroll
        for (int i = 0; i < 8; ++i) {                 // B: 2 splits x 1024 units
            int idx = i * 256 + tid, s = idx >> 10, rem = idx & 1023, row = rem >> 3, u = rem & 7;
            cpasync(bufb + 32768 + s * 16384 + SW128(row * 128 + u * 16),
                    &g_ws[s][((tap * 8 + cihi) * 512 + n0 + row) * 64 + u * 8], 16);
        }
        asm volatile("cp.async.commit_group;" ::: "memory");
    };

    issue(0);
    for (int stage = 0; stage < 216; ++stage) {
        if (stage + 1 < 216) {
            issue(stage + 1);
            asm volatile("cp.async.wait_group 1;" ::: "memory");
        } else {
            asm volatile("cp.async.wait_group 0;" ::: "memory");
        }
        __syncthreads();
        uint32_t bufb = sb + (stage & 1) * 65536;

        #pragma unroll
        for (int k16 = 0; k16 < 4; ++k16) {
            const int kb = k16 * 16;
            uint32_t bfr[2][8];
            #pragma unroll
            for (int s = 0; s < 2; ++s) {
                uint32_t bbase = bufb + 32768 + s * 16384;
                #pragma unroll
                for (int p = 0; p < 2; ++p) {
                    uint32_t ad = bbase + SW128((n_off + p * 16 + b_rl) * 128 + (kb + b_ko) * 2);
                    ldmx4(bfr[s][4 * p], bfr[s][4 * p + 1], bfr[s][4 * p + 2], bfr[s][4 * p + 3], ad);
                }
            }
            // sa = 0: products 00 -> accA, 01 -> accB
            {
                uint32_t af[4][4];
                #pragma unroll
                for (int mi = 0; mi < 4; ++mi) {
                    uint32_t ad = bufb + SW128((m_off + mi * 16 + a_rl) * 128 + (kb + a_ko) * 2);
                    ldmx4(af[mi][0], af[mi][1], af[mi][2], af[mi][3], ad);
                }
                #pragma unroll
                for (int mi = 0; mi < 4; ++mi)
                    #pragma unroll
                    for (int ni = 0; ni < 4; ++ni) {
                        mma16816(accA[mi][ni], af[mi], bfr[0][2 * ni], bfr[0][2 * ni + 1]);
                        mma16816(accB[mi][ni], af[mi], bfr[1][2 * ni], bfr[1][2 * ni + 1]);
                    }
            }
            // sa = 1: product 10 -> accB
            {
                uint32_t af[4][4];
                #pragma unroll
                for (int mi = 0; mi < 4; ++mi) {
                    uint32_t ad = bufb + 16384 + SW128((m_off + mi * 16 + a_rl) * 128 + (kb + a_ko) * 2);
                    ldmx4(af[mi][0], af[mi][1], af[mi][2], af[mi][3], ad);
                }
                #pragma unroll
                for (int mi = 0; mi < 4; ++mi)
                    #pragma unroll
                    for (int ni = 0; ni < 4; ++ni)
                        mma16816(accB[mi][ni], af[mi], bfr[0][2 * ni], bfr[0][2 * ni + 1]);
            }
        }

        // hierarchical merge: accA -> smem outer every 4 stages (own slice, no sync)
        if ((stage & 3) == 3) {
            #pragma unroll
            for (int mi = 0; mi < 4; ++mi)
                #pragma unroll
                for (int ni = 0; ni < 4; ++ni)
                    #pragma unroll
                    for (int r = 0; r < 4; ++r) {
                        int idx = (mi * 16 + ni * 4 + r) * 256 + tid;
                        s_oac[idx] += accA[mi][ni][r];
                        accA[mi][ni][r] = 0.f;
                    }
        }
        __syncthreads();
    }

    #pragma unroll
    for (int mi = 0; mi < 4; ++mi)
        #pragma unroll
        for (int ni = 0; ni < 4; ++ni)
            #pragma unroll
            for (int r = 0; r < 4; ++r) {
                int m  = m0 + m_off + mi * 16 + (lane >> 2) + 8 * (r >> 1);
                int co = n0 + n_off + ni * 8 + ((lane & 3) << 1) + (r & 1);
                float v = s_oac[(mi * 16 + ni * 4 + r) * 256 + tid]
                        + accB[mi][ni][r] * 4.8828125e-4f;  // 2^-11
                g_rpn[m * 512 + co] = fmaxf(v + __ldg(&bias[co]), 0.f);
            }
}

__global__ __launch_bounds__(256) void k_head(const float* __restrict__ bc,
                                              const float* __restrict__ bb,
                                              float* __restrict__ out_bbox) {
    __shared__ float As[16][132];
    __shared__ float Bs[16][48];
    const int tid = threadIdx.x, m0 = blockIdx.x * 128, n0 = blockIdx.y * 48;
    const int tx = tid & 15, ty = tid >> 4, lm = tid >> 1, lkq = (tid & 1) << 2;
    float oac[8][3], cmp[8][3];
    #pragma unroll
    for (int i = 0; i < 8; ++i)
        #pragma unroll
        for (int c = 0; c < 3; ++c) { oac[i][c] = 0.f; cmp[i][c] = 0.f; }
    for (int kk = 0; kk < 32; ++kk) {
        float4 a0 = *(const float4*)&g_rpn[(m0 + lm) * 512 + (kk << 4) + lkq];
        float4 a1 = *(const float4*)&g_rpn[(m0 + lm) * 512 + (kk << 4) + lkq + 8];
        float4 bw = make_float4(0.f, 0.f, 0.f, 0.f);
        int bk = 0, bn = 0;
        if (tid < 192) {
            bk = tid / 12; bn = (tid - bk * 12) << 2;
            bw = *(const float4*)&g_whead[((kk << 4) + bk) * 144 + n0 + bn];
        }
        __syncthreads();
        As[lkq + 0][lm] = a0.x;  As[lkq + 1][lm] = a0.y;  As[lkq + 2][lm] = a0.z;  As[lkq + 3][lm] = a0.w;
        As[lkq + 8][lm] = a1.x;  As[lkq + 9][lm] = a1.y;  As[lkq + 10][lm] = a1.z; As[lkq + 11][lm] = a1.w;
        if (tid < 192) *(float4*)&Bs[bk][bn] = bw;
        __syncthreads();
        float inn[8][3];
        #pragma unroll
        for (int i = 0; i < 8; ++i)
            #pragma unroll
            for (int c = 0; c < 3; ++c) inn[i][c] = 0.f;
        #pragma unroll
        for (int k = 0; k < 16; ++k) {
            float4 av0 = *(const float4*)&As[k][ty << 3];
            float4 av1 = *(const float4*)&As[k][(ty << 3) + 4];
            float b0 = Bs[k][tx * 3], b1 = Bs[k][tx * 3 + 1], b2 = Bs[k][tx * 3 + 2];
            float am[8] = {av0.x, av0.y, av0.z, av0.w, av1.x, av1.y, av1.z, av1.w};
            #pragma unroll
            for (int i = 0; i < 8; ++i) {
                inn[i][0] += am[i] * b0; inn[i][1] += am[i] * b1; inn[i][2] += am[i] * b2;
            }
        }
        #pragma unroll
        for (int i = 0; i < 8; ++i)
            #pragma unroll
            for (int c = 0; c < 3; ++c) {
                float y = inn[i][c] - cmp[i][c], t = oac[i][c] + y;
                cmp[i][c] = (t - oac[i][c]) - y; oac[i][c] = t;
            }
    }
    #pragma unroll
    for (int i = 0; i < 8; ++i) {
        int m = m0 + (ty << 3) + i, b = m / THW, pos = m - b * THW;
        #pragma unroll
        for (int c = 0; c < 3; ++c) {
            int n = n0 + tx * 3 + c;
            float v = oac[i][c] + cmp[i][c];
            if (n < 36) g_cls[(b * 36 + n) * THW + pos] = v + bc[n];
            else        out_bbox[(b * 108 + (n - 36)) * THW + pos] = v + bb[n - 36];
        }
    }
}

__global__ void k_prob(float* __restrict__ out_prob) {
    int i = blockIdx.x * 256 + threadIdx.x;
    if (i >= 8 * NPROP) return;
    int b = i / NPROP, r = i - b * NPROP, pos = r / 18, a = r - pos * 18;
    float s0 = g_cls[(b * 36 + a) * THW + pos];
    float s1 = g_cls[(b * 36 + 18 + a) * THW + pos];
    float mx = fmaxf(s0, s1);
    float e0 = expf(s0 - mx), e1 = expf(s1 - mx), s = e0 + e1;
    out_prob[(b * 36 + a) * THW + pos]      = e0 / s;
    out_prob[(b * 36 + 18 + a) * THW + pos] = e1 / s;
    g_okey[b * NPROP + r] = okey(e1 / s);
}

__global__ void k_prop(const float* __restrict__ anchors, const float* __restrict__ im_info,
                       const float* __restrict__ bbox) {
    int i = blockIdx.x * 256 + threadIdx.x;
    if (i >= 8 * NPROP) return;
    int b = i / NPROP, r = i - b * NPROP, pos = r / 18, a = r - pos * 18;
    const float* an = &anchors[r * 6];
    float aw = an[3] - an[0] + 1.f, ah = an[4] - an[1] + 1.f, al = an[5] - an[2] + 1.f;
    float cx = an[0] + 0.5f * aw, cy = an[1] + 0.5f * ah, ct = an[2] + 0.5f * al;
    const float* dp = &bbox[(b * 108 + a * 6) * THW + pos];
    float pcx = dp[0] * aw + cx, pcy = dp[THW] * ah + cy, pct = dp[2 * THW] * al + ct;
    float pw = expf(dp[3 * THW]) * aw, ph = expf(dp[4 * THW]) * ah, pl = expf(dp[5 * THW]) * al;
    float hx = im_info[b * 3 + 1] - 1.f, hy = im_info[b * 3 + 0] - 1.f;
    float* o = &g_props[(b * NPROP + r) * 6];
    o[0] = fminf(fmaxf(pcx - 0.5f * pw, 0.f), hx);
    o[1] = fminf(fmaxf(pcy - 0.5f * ph, 0.f), hy);
    o[2] = fminf(fmaxf(pct - 0.5f * pl, 0.f), 15.f);
    o[3] = fminf(fmaxf(pcx + 0.5f * pw, 0.f), hx);
    o[4] = fminf(fmaxf(pcy + 0.5f * ph, 0.f), hy);
    o[5] = fminf(fmaxf(pct + 0.5f * pl, 0.f), 15.f);
}

__global__ __launch_bounds__(1024) void k_topk(float* __restrict__ out) {
    const int b = blockIdx.x, tid = threadIdx.x;
    const unsigned* key = g_okey + b * NPROP;
    __shared__ int s_cnt, n_gt, n_eq;
    __shared__ unsigned s_lo, s_hi;
    __shared__ int win[300];
    __shared__ int eq_buf[4096];
    __shared__ unsigned long long skey[512];
    if (tid == 0) { s_lo = 0u; s_hi = 0xFFFFFFFFu; }
    __syncthreads();
    for (int it = 0; it < 32; ++it) {
        unsigned lo = s_lo, hi = s_hi;
        unsigned mid = lo + (unsigned)((((unsigned long long)hi - lo + 1ull)) >> 1);
        if (tid == 0) s_cnt = 0;
        __syncthreads();
        int c = 0;
        for (int i = tid; i < NPROP; i += 1024) c += (key[i] >= mid);
        #pragma unroll
        for (int o = 16; o > 0; o >>= 1) c += __shfl_down_sync(0xffffffffu, c, o);
        if ((tid & 31) == 0) atomicAdd(&s_cnt, c);
        __syncthreads();
        if (tid == 0) { if (s_cnt >= 300) s_lo = mid; else s_hi = mid - 1u; }
        __syncthreads();
    }
    const unsigned V = s_lo;
    if (tid == 0) { n_gt = 0; n_eq = 0; }
    __syncthreads();
    for (int i = tid; i < NPROP; i += 1024) {
        unsigned u = key[i];
        if (u > V)       { int p = atomicAdd(&n_gt, 1); win[p] = i; }
        else if (u == V) { int p = atomicAdd(&n_eq, 1); if (p < 4096) eq_buf[p] = i; }
    }
    __syncthreads();
    const int need = 300 - n_gt;
    const int ne = (n_eq < 4096) ? n_eq : 4096;
    for (int j = tid; j < ne; j += 1024) {
        int v = eq_buf[j], rk = 0;
        for (int q = 0; q < ne; ++q) rk += (eq_buf[q] < v);
        if (rk < need) win[n_gt + rk] = v;
    }
    __syncthreads();
    for (int i = tid; i < 512; i += 1024) {
        if (i < 300) {
            int idx = win[i];
            skey[i] = ((unsigned long long)key[idx] << 32) | (unsigned)(~(unsigned)idx);
        } else skey[i] = 0ull;
    }
    __syncthreads();
    for (int ks = 2; ks <= 512; ks <<= 1)
        for (int js = ks >> 1; js > 0; js >>= 1) {
            if (tid < 512) {
                int i = tid, ixj = i ^ js;
                if (ixj > i) {
                    unsigned long long A = skey[i], B2 = skey[ixj];
                    bool up = (i & ks) == 0;
                    if (up ? (A < B2) : (A > B2)) { skey[i] = B2; skey[ixj] = A; }
                }
            }
            __syncthreads();
        }
    for (int r = tid; r < 300; r += 1024) {
        int idx = (int)(~(unsigned)skey[r]);
        const float* p = &g_props[(b * NPROP + idx) * 6];
        float* o = out + (b * 300 + r) * 7;
        o[0] = (float)b;
        o[1] = p[0]; o[2] = p[1]; o[3] = p[2]; o[4] = p[3]; o[5] = p[4]; o[6] = p[5];
    }
}

extern "C" void kernel_launch(void* const* d_in, const int* in_sizes, int n_in,
                              void* d_out, int out_size) {
    const float* base_feat = (const float*)d_in[0];
    const float* im_info   = (const float*)d_in[1];
    const float* W_conv    = (const float*)d_in[2];
    const float* b_conv    = (const float*)d_in[3];
    const float* W_cls     = (const float*)d_in[4];
    const float* b_cls     = (const float*)d_in[5];
    const float* W_bbox    = (const float*)d_in[6];
    const float* b_bbox    = (const float*)d_in[7];
    const float* anchors   = (const float*)d_in[8];
    float* out = (float*)d_out;

    cudaFuncSetAttribute(k_conv_mma, cudaFuncAttributeMaxDynamicSharedMemorySize, SMEM_CONV);
    k_split_x<<<dim3(150, 16, 8), 256>>>(base_feat);
    k_split_w<<<1024, 256>>>(W_conv);
    k_whead<<<288, 256>>>(W_cls, W_bbox);
    k_conv_mma<<<dim3(300, 4), 256, SMEM_CONV>>>(b_conv);
    k_head<<<dim3(300, 3), 256>>>(b_cls, b_bbox, out + OUT_BBOX);
    k_prob<<<2700, 256>>>(out + OUT_PROB);
    k_prop<<<2700, 256>>>(anchors, im_info, out + OUT_BBOX);
    k_topk<<<8, 1024>>>(out);
}

// round 14
// speedup vs baseline: 2.6318x; 1.0565x over previous
#include <cuda_runtime.h>
#include <cuda_fp16.h>
#include <cstdint>

#define THW   4800
#define NPROP 86400
#define OUT_PROB 16800
#define OUT_BBOX (16800 + 1382400)

__device__ __half  g_xs[2][8 * THW * 512];
__device__ __half  g_ws[2][27 * 8 * 512 * 64];
__device__ float    g_rpn[8 * THW * 512];
__device__ float    g_whead[512 * 144];
__device__ float    g_cls[8 * 36 * THW];
__device__ unsigned g_okey[8 * NPROP];
__device__ float    g_props[8 * NPROP * 6];

__device__ __forceinline__ uint32_t smem_u32(const void* p) {
    uint32_t a;
    asm("{ .reg .u64 t; cvta.to.shared.u64 t, %1; cvt.u32.u64 %0, t; }" : "=r"(a) : "l"(p));
    return a;
}
__device__ __forceinline__ unsigned okey(float f) {
    unsigned u = __float_as_uint(f);
    return (u & 0x80000000u) ? ~u : (u | 0x80000000u);
}
#define SW128(o) ((o) ^ (((o) >> 3) & 0x70))

__device__ __forceinline__ void ldmx4(uint32_t& r0, uint32_t& r1, uint32_t& r2, uint32_t& r3, uint32_t ad) {
    asm volatile("ldmatrix.sync.aligned.m8n8.x4.shared.b16 {%0,%1,%2,%3}, [%4];"
                 : "=r"(r0), "=r"(r1), "=r"(r2), "=r"(r3) : "r"(ad));
}
__device__ __forceinline__ void mma16816(float* c, const uint32_t* a, uint32_t b0, uint32_t b1) {
    asm volatile("mma.sync.aligned.m16n8k16.row.col.f32.f16.f16.f32 "
                 "{%0,%1,%2,%3}, {%4,%5,%6,%7}, {%8,%9}, {%0,%1,%2,%3};"
                 : "+f"(c[0]), "+f"(c[1]), "+f"(c[2]), "+f"(c[3])
                 : "r"(a[0]), "r"(a[1]), "r"(a[2]), "r"(a[3]), "r"(b0), "r"(b1));
}
__device__ __forceinline__ void cpasync(uint32_t dst, const void* src, uint32_t sz) {
    asm volatile("cp.async.cg.shared.global [%0], [%1], 16, %2;" :: "r"(dst), "l"(src), "r"(sz) : "memory");
}
// fp16 2-split: v = h0 + h1 * 2^-11  (h1 stored pre-scaled by 2^11)
__device__ __forceinline__ void split2(float v, __half& h0, __half& h1) {
    h0 = __float2half_rn(v);
    h1 = __float2half_rn((v - __half2float(h0)) * 2048.0f);
}

__global__ void k_split_x(const float* __restrict__ x) {
    __shared__ float tile[32][33];
    int b = blockIdx.z, p0 = blockIdx.x * 32, c0 = blockIdx.y * 32;
    int tx = threadIdx.x & 31, ty = threadIdx.x >> 5;
    #pragma unroll
    for (int j = 0; j < 4; ++j)
        tile[ty + 8 * j][tx] = x[(b * 512 + c0 + ty + 8 * j) * THW + p0 + tx];
    __syncthreads();
    #pragma unroll
    for (int j = 0; j < 4; ++j) {
        __half h0, h1;
        split2(tile[tx][ty + 8 * j], h0, h1);
        int o = (b * THW + p0 + ty + 8 * j) * 512 + c0 + tx;
        g_xs[0][o] = h0; g_xs[1][o] = h1;
    }
}

__global__ void k_split_w(const float* __restrict__ w) {
    int i = blockIdx.x * 256 + threadIdx.x;
    if (i >= 512 * 512) return;
    int co = i >> 9, ci = i & 511;
    #pragma unroll 1
    for (int tap = 0; tap < 27; ++tap) {
        __half h0, h1;
        split2(w[i * 27 + tap], h0, h1);
        int o = ((tap * 8 + (ci >> 6)) * 512 + co) * 64 + (ci & 63);
        g_ws[0][o] = h0; g_ws[1][o] = h1;
    }
}

__global__ void k_whead(const float* __restrict__ wc, const float* __restrict__ wb) {
    int i = blockIdx.x * 256 + threadIdx.x;
    if (i >= 512 * 144) return;
    int k = i / 144, n = i - k * 144;
    g_whead[i] = (n < 36) ? __ldg(&wc[n * 512 + k]) : __ldg(&wb[(n - 36) * 512 + k]);
}

// conv: mma.sync fp16 2-split, 512 thr / 16 warps (warp tile 64x16), smem outer acc.
// grid(300,4), 216 stages. smem: 128KB staging + s_pk + 64KB oac.
#define SMEM_CONV (131072 + 512 + 65536)
__global__ __launch_bounds__(512, 1) void k_conv_mma(const float* __restrict__ bias) {
    extern __shared__ __align__(1024) char smem[];
    const int tid = threadIdx.x, wid = tid >> 5, lane = tid & 31;
    const int m0 = blockIdx.x * 128, n0 = blockIdx.y * 128;
    const uint32_t sb = smem_u32(smem);
    int*   s_pk  = (int*)(smem + 131072);
    float* s_oac = (float*)(smem + 131584);   // [32][512] thread-strided

    if (tid < 128) {
        int m = m0 + tid, b = m / THW, pos = m - b * THW;
        int t = pos / 300, r = pos - t * 300, h = r / 20, w = r - h * 20;
        s_pk[tid] = t | (h << 8) | (w << 16) | (b << 24);
    }
    #pragma unroll
    for (int i = 0; i < 32; ++i) s_oac[i * 512 + tid] = 0.f;
    __syncthreads();

    const int m_off = (wid & 1) * 64, n_off = (wid >> 1) * 16;
    const int a_rl = (lane & 7) + 8 * ((lane >> 3) & 1), a_ko = 8 * (lane >> 4);
    const int b_rl = (lane & 7) + 8 * (lane >> 4),       b_ko = 8 * ((lane >> 3) & 1);

    float accA[4][2][4], accB[4][2][4];
    #pragma unroll
    for (int mi = 0; mi < 4; ++mi)
        #pragma unroll
        for (int ni = 0; ni < 2; ++ni)
            #pragma unroll
            for (int r = 0; r < 4; ++r) { accA[mi][ni][r] = 0.f; accB[mi][ni][r] = 0.f; }

    auto issue = [&](int stage) {
        int tap = stage >> 3, cihi = stage & 7;
        int dt = tap / 9 - 1, rm = tap % 9, dh = rm / 3 - 1, dw = rm % 3 - 1;
        uint32_t bufb = sb + (stage & 1) * 65536;
        #pragma unroll
        for (int i = 0; i < 4; ++i) {                 // A: 2 splits x 1024 units
            int idx = i * 512 + tid, s = idx >> 10, rem = idx & 1023, row = rem >> 3, u = rem & 7;
            int pk = s_pk[row];
            int t = (pk & 255) + dt, h = ((pk >> 8) & 255) + dh, w = ((pk >> 16) & 255) + dw;
            const __half* src = &g_xs[s][0];
            uint32_t sz = 0;
            if ((unsigned)t < 16u && (unsigned)h < 15u && (unsigned)w < 20u) {
                src = &g_xs[s][(((pk >> 24) & 255) * THW + (t * 15 + h) * 20 + w) * 512 + cihi * 64 + u * 8];
                sz = 16;
            }
            cpasync(bufb + s * 16384 + SW128(row * 128 + u * 16), src, sz);
        }
        #pragma unroll
        for (int i = 0; i < 4; ++i) {                 // B: 2 splits x 1024 units
            int idx = i * 512 + tid, s = idx >> 10, rem = idx & 1023, row = rem >> 3, u = rem & 7;
            cpasync(bufb + 32768 + s * 16384 + SW128(row * 128 + u * 16),
                    &g_ws[s][((tap * 8 + cihi) * 512 + n0 + row) * 64 + u * 8], 16);
        }
        asm volatile("cp.async.commit_group;" ::: "memory");
    };

    issue(0);
    for (int stage = 0; stage < 216; ++stage) {
        if (stage + 1 < 216) {
            issue(stage + 1);
            asm volatile("cp.async.wait_group 1;" ::: "memory");
        } else {
            asm volatile("cp.async.wait_group 0;" ::: "memory");
        }
        __syncthreads();
        uint32_t bufb = sb + (stage & 1) * 65536;

        #pragma unroll
        for (int k16 = 0; k16 < 4; ++k16) {
            const int kb = k16 * 16;
            uint32_t bfr[2][4];
            #pragma unroll
            for (int s = 0; s < 2; ++s) {
                uint32_t ad = bufb + 32768 + s * 16384
                            + SW128((n_off + b_rl) * 128 + (kb + b_ko) * 2);
                ldmx4(bfr[s][0], bfr[s][1], bfr[s][2], bfr[s][3], ad);
            }
            // sa = 0: products 00 -> accA, 01 -> accB
            {
                uint32_t af[4][4];
                #pragma unroll
                for (int mi = 0; mi < 4; ++mi) {
                    uint32_t ad = bufb + SW128((m_off + mi * 16 + a_rl) * 128 + (kb + a_ko) * 2);
                    ldmx4(af[mi][0], af[mi][1], af[mi][2], af[mi][3], ad);
                }
                #pragma unroll
                for (int mi = 0; mi < 4; ++mi)
                    #pragma unroll
                    for (int ni = 0; ni < 2; ++ni) {
                        mma16816(accA[mi][ni], af[mi], bfr[0][2 * ni], bfr[0][2 * ni + 1]);
                        mma16816(accB[mi][ni], af[mi], bfr[1][2 * ni], bfr[1][2 * ni + 1]);
                    }
            }
            // sa = 1: product 10 -> accB
            {
                uint32_t af[4][4];
                #pragma unroll
                for (int mi = 0; mi < 4; ++mi) {
                    uint32_t ad = bufb + 16384 + SW128((m_off + mi * 16 + a_rl) * 128 + (kb + a_ko) * 2);
                    ldmx4(af[mi][0], af[mi][1], af[mi][2], af[mi][3], ad);
                }
                #pragma unroll
                for (int mi = 0; mi < 4; ++mi)
                    #pragma unroll
                    for (int ni = 0; ni < 2; ++ni)
                        mma16816(accB[mi][ni], af[mi], bfr[0][2 * ni], bfr[0][2 * ni + 1]);
            }
        }

        // hierarchical merge: accA -> smem outer every 4 stages (own slice, no sync)
        if ((stage & 3) == 3) {
            #pragma unroll
            for (int mi = 0; mi < 4; ++mi)
                #pragma unroll
                for (int ni = 0; ni < 2; ++ni)
                    #pragma unroll
                    for (int r = 0; r < 4; ++r) {
                        int idx = (mi * 8 + ni * 4 + r) * 512 + tid;
                        s_oac[idx] += accA[mi][ni][r];
                        accA[mi][ni][r] = 0.f;
                    }
        }
        __syncthreads();
    }

    #pragma unroll
    for (int mi = 0; mi < 4; ++mi)
        #pragma unroll
        for (int ni = 0; ni < 2; ++ni)
            #pragma unroll
            for (int r = 0; r < 4; ++r) {
                int m  = m0 + m_off + mi * 16 + (lane >> 2) + 8 * (r >> 1);
                int co = n0 + n_off + ni * 8 + ((lane & 3) << 1) + (r & 1);
                float v = s_oac[(mi * 8 + ni * 4 + r) * 512 + tid]
                        + accB[mi][ni][r] * 4.8828125e-4f;  // 2^-11
                g_rpn[m * 512 + co] = fmaxf(v + __ldg(&bias[co]), 0.f);
            }
}

__global__ __launch_bounds__(256) void k_head(const float* __restrict__ bc,
                                              const float* __restrict__ bb,
                                              float* __restrict__ out_bbox) {
    __shared__ float As[16][132];
    __shared__ float Bs[16][48];
    const int tid = threadIdx.x, m0 = blockIdx.x * 128, n0 = blockIdx.y * 48;
    const int tx = tid & 15, ty = tid >> 4, lm = tid >> 1, lkq = (tid & 1) << 2;
    float oac[8][3], cmp[8][3];
    #pragma unroll
    for (int i = 0; i < 8; ++i)
        #pragma unroll
        for (int c = 0; c < 3; ++c) { oac[i][c] = 0.f; cmp[i][c] = 0.f; }
    for (int kk = 0; kk < 32; ++kk) {
        float4 a0 = *(const float4*)&g_rpn[(m0 + lm) * 512 + (kk << 4) + lkq];
        float4 a1 = *(const float4*)&g_rpn[(m0 + lm) * 512 + (kk << 4) + lkq + 8];
        float4 bw = make_float4(0.f, 0.f, 0.f, 0.f);
        int bk = 0, bn = 0;
        if (tid < 192) {
            bk = tid / 12; bn = (tid - bk * 12) << 2;
            bw = *(const float4*)&g_whead[((kk << 4) + bk) * 144 + n0 + bn];
        }
        __syncthreads();
        As[lkq + 0][lm] = a0.x;  As[lkq + 1][lm] = a0.y;  As[lkq + 2][lm] = a0.z;  As[lkq + 3][lm] = a0.w;
        As[lkq + 8][lm] = a1.x;  As[lkq + 9][lm] = a1.y;  As[lkq + 10][lm] = a1.z; As[lkq + 11][lm] = a1.w;
        if (tid < 192) *(float4*)&Bs[bk][bn] = bw;
        __syncthreads();
        float inn[8][3];
        #pragma unroll
        for (int i = 0; i < 8; ++i)
            #pragma unroll
            for (int c = 0; c < 3; ++c) inn[i][c] = 0.f;
        #pragma unroll
        for (int k = 0; k < 16; ++k) {
            float4 av0 = *(const float4*)&As[k][ty << 3];
            float4 av1 = *(const float4*)&As[k][(ty << 3) + 4];
            float b0 = Bs[k][tx * 3], b1 = Bs[k][tx * 3 + 1], b2 = Bs[k][tx * 3 + 2];
            float am[8] = {av0.x, av0.y, av0.z, av0.w, av1.x, av1.y, av1.z, av1.w};
            #pragma unroll
            for (int i = 0; i < 8; ++i) {
                inn[i][0] += am[i] * b0; inn[i][1] += am[i] * b1; inn[i][2] += am[i] * b2;
            }
        }
        #pragma unroll
        for (int i = 0; i < 8; ++i)
            #pragma unroll
            for (int c = 0; c < 3; ++c) {
                float y = inn[i][c] - cmp[i][c], t = oac[i][c] + y;
                cmp[i][c] = (t - oac[i][c]) - y; oac[i][c] = t;
            }
    }
    #pragma unroll
    for (int i = 0; i < 8; ++i) {
        int m = m0 + (ty << 3) + i, b = m / THW, pos = m - b * THW;
        #pragma unroll
        for (int c = 0; c < 3; ++c) {
            int n = n0 + tx * 3 + c;
            float v = oac[i][c] + cmp[i][c];
            if (n < 36) g_cls[(b * 36 + n) * THW + pos] = v + bc[n];
            else        out_bbox[(b * 108 + (n - 36)) * THW + pos] = v + bb[n - 36];
        }
    }
}

__global__ void k_prob(float* __restrict__ out_prob) {
    int i = blockIdx.x * 256 + threadIdx.x;
    if (i >= 8 * NPROP) return;
    int b = i / NPROP, r = i - b * NPROP, pos = r / 18, a = r - pos * 18;
    float s0 = g_cls[(b * 36 + a) * THW + pos];
    float s1 = g_cls[(b * 36 + 18 + a) * THW + pos];
    float mx = fmaxf(s0, s1);
    float e0 = expf(s0 - mx), e1 = expf(s1 - mx), s = e0 + e1;
    out_prob[(b * 36 + a) * THW + pos]      = e0 / s;
    out_prob[(b * 36 + 18 + a) * THW + pos] = e1 / s;
    g_okey[b * NPROP + r] = okey(e1 / s);
}

__global__ void k_prop(const float* __restrict__ anchors, const float* __restrict__ im_info,
                       const float* __restrict__ bbox) {
    int i = blockIdx.x * 256 + threadIdx.x;
    if (i >= 8 * NPROP) return;
    int b = i / NPROP, r = i - b * NPROP, pos = r / 18, a = r - pos * 18;
    const float* an = &anchors[r * 6];
    float aw = an[3] - an[0] + 1.f, ah = an[4] - an[1] + 1.f, al = an[5] - an[2] + 1.f;
    float cx = an[0] + 0.5f * aw, cy = an[1] + 0.5f * ah, ct = an[2] + 0.5f * al;
    const float* dp = &bbox[(b * 108 + a * 6) * THW + pos];
    float pcx = dp[0] * aw + cx, pcy = dp[THW] * ah + cy, pct = dp[2 * THW] * al + ct;
    float pw = expf(dp[3 * THW]) * aw, ph = expf(dp[4 * THW]) * ah, pl = expf(dp[5 * THW]) * al;
    float hx = im_info[b * 3 + 1] - 1.f, hy = im_info[b * 3 + 0] - 1.f;
    float* o = &g_props[(b * NPROP + r) * 6];
    o[0] = fminf(fmaxf(pcx - 0.5f * pw, 0.f), hx);
    o[1] = fminf(fmaxf(pcy - 0.5f * ph, 0.f), hy);
    o[2] = fminf(fmaxf(pct - 0.5f * pl, 0.f), 15.f);
    o[3] = fminf(fmaxf(pcx + 0.5f * pw, 0.f), hx);
    o[4] = fminf(fmaxf(pcy + 0.5f * ph, 0.f), hy);
    o[5] = fminf(fmaxf(pct + 0.5f * pl, 0.f), 15.f);
}

__global__ __launch_bounds__(1024) void k_topk(float* __restrict__ out) {
    const int b = blockIdx.x, tid = threadIdx.x;
    const unsigned* key = g_okey + b * NPROP;
    __shared__ int s_cnt, n_gt, n_eq;
    __shared__ unsigned s_lo, s_hi;
    __shared__ int win[300];
    __shared__ int eq_buf[4096];
    __shared__ unsigned long long skey[512];
    if (tid == 0) { s_lo = 0u; s_hi = 0xFFFFFFFFu; }
    __syncthreads();
    for (int it = 0; it < 32; ++it) {
        unsigned lo = s_lo, hi = s_hi;
        unsigned mid = lo + (unsigned)((((unsigned long long)hi - lo + 1ull)) >> 1);
        if (tid == 0) s_cnt = 0;
        __syncthreads();
        int c = 0;
        for (int i = tid; i < NPROP; i += 1024) c += (key[i] >= mid);
        #pragma unroll
        for (int o = 16; o > 0; o >>= 1) c += __shfl_down_sync(0xffffffffu, c, o);
        if ((tid & 31) == 0) atomicAdd(&s_cnt, c);
        __syncthreads();
        if (tid == 0) { if (s_cnt >= 300) s_lo = mid; else s_hi = mid - 1u; }
        __syncthreads();
    }
    const unsigned V = s_lo;
    if (tid == 0) { n_gt = 0; n_eq = 0; }
    __syncthreads();
    for (int i = tid; i < NPROP; i += 1024) {
        unsigned u = key[i];
        if (u > V)       { int p = atomicAdd(&n_gt, 1); win[p] = i; }
        else if (u == V) { int p = atomicAdd(&n_eq, 1); if (p < 4096) eq_buf[p] = i; }
    }
    __syncthreads();
    const int need = 300 - n_gt;
    const int ne = (n_eq < 4096) ? n_eq : 4096;
    for (int j = tid; j < ne; j += 1024) {
        int v = eq_buf[j], rk = 0;
        for (int q = 0; q < ne; ++q) rk += (eq_buf[q] < v);
        if (rk < need) win[n_gt + rk] = v;
    }
    __syncthreads();
    for (int i = tid; i < 512; i += 1024) {
        if (i < 300) {
            int idx = win[i];
            skey[i] = ((unsigned long long)key[idx] << 32) | (unsigned)(~(unsigned)idx);
        } else skey[i] = 0ull;
    }
    __syncthreads();
    for (int ks = 2; ks <= 512; ks <<= 1)
        for (int js = ks >> 1; js > 0; js >>= 1) {
            if (tid < 512) {
                int i = tid, ixj = i ^ js;
                if (ixj > i) {
                    unsigned long long A = skey[i], B2 = skey[ixj];
                    bool up = (i & ks) == 0;
                    if (up ? (A < B2) : (A > B2)) { skey[i] = B2; skey[ixj] = A; }
                }
            }
            __syncthreads();
        }
    for (int r = tid; r < 300; r += 1024) {
        int idx = (int)(~(unsigned)skey[r]);
        const float* p = &g_props[(b * NPROP + idx) * 6];
        float* o = out + (b * 300 + r) * 7;
        o[0] = (float)b;
        o[1] = p[0]; o[2] = p[1]; o[3] = p[2]; o[4] = p[3]; o[5] = p[4]; o[6] = p[5];
    }
}

extern "C" void kernel_launch(void* const* d_in, const int* in_sizes, int n_in,
                              void* d_out, int out_size) {
    const float* base_feat = (const float*)d_in[0];
    const float* im_info   = (const float*)d_in[1];
    const float* W_conv    = (const float*)d_in[2];
    const float* b_conv    = (const float*)d_in[3];
    const float* W_cls     = (const float*)d_in[4];
    const float* b_cls     = (const float*)d_in[5];
    const float* W_bbox    = (const float*)d_in[6];
    const float* b_bbox    = (const float*)d_in[7];
    const float* anchors   = (const float*)d_in[8];
    float* out = (float*)d_out;

    cudaFuncSetAttribute(k_conv_mma, cudaFuncAttributeMaxDynamicSharedMemorySize, SMEM_CONV);
    k_split_x<<<dim3(150, 16, 8), 256>>>(base_feat);
    k_split_w<<<1024, 256>>>(W_conv);
    k_whead<<<288, 256>>>(W_cls, W_bbox);
    k_conv_mma<<<dim3(300, 4), 512, SMEM_CONV>>>(b_conv);
    k_head<<<dim3(300, 3), 256>>>(b_cls, b_bbox, out + OUT_BBOX);
    k_prob<<<2700, 256>>>(out + OUT_PROB);
    k_prop<<<2700, 256>>>(anchors, im_info, out + OUT_BBOX);
    k_topk<<<8, 1024>>>(out);
}

// round 15
// speedup vs baseline: 2.6431x; 1.0043x over previous
#include <cuda_runtime.h>
#include <cuda_fp16.h>
#include <cstdint>

#define THW   4800
#define NPROP 86400
#define OUT_PROB 16800
#define OUT_BBOX (16800 + 1382400)

__device__ __half  g_xs[2][8 * THW * 512];
__device__ __half  g_ws[2][27 * 8 * 512 * 64];
__device__ float    g_rpn[8 * THW * 512];
__device__ float    g_whead[512 * 144];
__device__ float    g_cls[8 * 36 * THW];
__device__ unsigned g_okey[8 * NPROP];
__device__ float    g_props[8 * NPROP * 6];

__device__ __forceinline__ uint32_t smem_u32(const void* p) {
    uint32_t a;
    asm("{ .reg .u64 t; cvta.to.shared.u64 t, %1; cvt.u32.u64 %0, t; }" : "=r"(a) : "l"(p));
    return a;
}
__device__ __forceinline__ unsigned okey(float f) {
    unsigned u = __float_as_uint(f);
    return (u & 0x80000000u) ? ~u : (u | 0x80000000u);
}
#define SW128(o) ((o) ^ (((o) >> 3) & 0x70))

__device__ __forceinline__ void ldmx4(uint32_t& r0, uint32_t& r1, uint32_t& r2, uint32_t& r3, uint32_t ad) {
    asm volatile("ldmatrix.sync.aligned.m8n8.x4.shared.b16 {%0,%1,%2,%3}, [%4];"
                 : "=r"(r0), "=r"(r1), "=r"(r2), "=r"(r3) : "r"(ad));
}
__device__ __forceinline__ void mma16816(float* c, const uint32_t* a, uint32_t b0, uint32_t b1) {
    asm volatile("mma.sync.aligned.m16n8k16.row.col.f32.f16.f16.f32 "
                 "{%0,%1,%2,%3}, {%4,%5,%6,%7}, {%8,%9}, {%0,%1,%2,%3};"
                 : "+f"(c[0]), "+f"(c[1]), "+f"(c[2]), "+f"(c[3])
                 : "r"(a[0]), "r"(a[1]), "r"(a[2]), "r"(a[3]), "r"(b0), "r"(b1));
}
__device__ __forceinline__ void cpasync(uint32_t dst, const void* src, uint32_t sz) {
    asm volatile("cp.async.cg.shared.global [%0], [%1], 16, %2;" :: "r"(dst), "l"(src), "r"(sz) : "memory");
}
// fp16 2-split: v = h0 + h1 * 2^-11  (h1 stored pre-scaled by 2^11)
__device__ __forceinline__ void split2(float v, __half& h0, __half& h1) {
    h0 = __float2half_rn(v);
    h1 = __float2half_rn((v - __half2float(h0)) * 2048.0f);
}

__global__ void k_split_x(const float* __restrict__ x) {
    __shared__ float tile[32][33];
    int b = blockIdx.z, p0 = blockIdx.x * 32, c0 = blockIdx.y * 32;
    int tx = threadIdx.x & 31, ty = threadIdx.x >> 5;
    #pragma unroll
    for (int j = 0; j < 4; ++j)
        tile[ty + 8 * j][tx] = x[(b * 512 + c0 + ty + 8 * j) * THW + p0 + tx];
    __syncthreads();
    #pragma unroll
    for (int j = 0; j < 4; ++j) {
        __half h0, h1;
        split2(tile[tx][ty + 8 * j], h0, h1);
        int o = (b * THW + p0 + ty + 8 * j) * 512 + c0 + tx;
        g_xs[0][o] = h0; g_xs[1][o] = h1;
    }
}

__global__ void k_split_w(const float* __restrict__ w) {
    int i = blockIdx.x * 256 + threadIdx.x;
    if (i >= 512 * 512) return;
    int co = i >> 9, ci = i & 511;
    #pragma unroll 1
    for (int tap = 0; tap < 27; ++tap) {
        __half h0, h1;
        split2(w[i * 27 + tap], h0, h1);
        int o = ((tap * 8 + (ci >> 6)) * 512 + co) * 64 + (ci & 63);
        g_ws[0][o] = h0; g_ws[1][o] = h1;
    }
}

__global__ void k_whead(const float* __restrict__ wc, const float* __restrict__ wb) {
    int i = blockIdx.x * 256 + threadIdx.x;
    if (i >= 512 * 144) return;
    int k = i / 144, n = i - k * 144;
    g_whead[i] = (n < 36) ? __ldg(&wc[n * 512 + k]) : __ldg(&wb[(n - 36) * 512 + k]);
}

// conv: mma.sync fp16 2-split, 512 thr / 16 warps (warp tile 32x32, 4m x 4n), smem outer acc.
// grid(300,4), 216 stages. smem: 128KB staging + s_pk + 64KB oac.
#define SMEM_CONV (131072 + 512 + 65536)
__global__ __launch_bounds__(512, 1) void k_conv_mma(const float* __restrict__ bias) {
    extern __shared__ __align__(1024) char smem[];
    const int tid = threadIdx.x, wid = tid >> 5, lane = tid & 31;
    const int m0 = blockIdx.x * 128, n0 = blockIdx.y * 128;
    const uint32_t sb = smem_u32(smem);
    int*   s_pk  = (int*)(smem + 131072);
    float* s_oac = (float*)(smem + 131584);   // [32][512] thread-strided

    if (tid < 128) {
        int m = m0 + tid, b = m / THW, pos = m - b * THW;
        int t = pos / 300, r = pos - t * 300, h = r / 20, w = r - h * 20;
        s_pk[tid] = t | (h << 8) | (w << 16) | (b << 24);
    }
    #pragma unroll
    for (int i = 0; i < 32; ++i) s_oac[i * 512 + tid] = 0.f;
    __syncthreads();

    const int m_off = (wid & 3) * 32, n_off = (wid >> 2) * 32;
    const int a_rl = (lane & 7) + 8 * ((lane >> 3) & 1), a_ko = 8 * (lane >> 4);
    const int b_rl = (lane & 7) + 8 * (lane >> 4),       b_ko = 8 * ((lane >> 3) & 1);

    float accA[2][4][4], accB[2][4][4];
    #pragma unroll
    for (int mi = 0; mi < 2; ++mi)
        #pragma unroll
        for (int nj = 0; nj < 4; ++nj)
            #pragma unroll
            for (int r = 0; r < 4; ++r) { accA[mi][nj][r] = 0.f; accB[mi][nj][r] = 0.f; }

    auto issue = [&](int stage) {
        int tap = stage >> 3, cihi = stage & 7;
        int dt = tap / 9 - 1, rm = tap % 9, dh = rm / 3 - 1, dw = rm % 3 - 1;
        uint32_t bufb = sb + (stage & 1) * 65536;
        #pragma unroll
        for (int i = 0; i < 4; ++i) {                 // A: 2 splits x 1024 units
            int idx = i * 512 + tid, s = idx >> 10, rem = idx & 1023, row = rem >> 3, u = rem & 7;
            int pk = s_pk[row];
            int t = (pk & 255) + dt, h = ((pk >> 8) & 255) + dh, w = ((pk >> 16) & 255) + dw;
            const __half* src = &g_xs[s][0];
            uint32_t sz = 0;
            if ((unsigned)t < 16u && (unsigned)h < 15u && (unsigned)w < 20u) {
                src = &g_xs[s][(((pk >> 24) & 255) * THW + (t * 15 + h) * 20 + w) * 512 + cihi * 64 + u * 8];
                sz = 16;
            }
            cpasync(bufb + s * 16384 + SW128(row * 128 + u * 16), src, sz);
        }
        #pragma unroll
        for (int i = 0; i < 4; ++i) {                 // B: 2 splits x 1024 units
            int idx = i * 512 + tid, s = idx >> 10, rem = idx & 1023, row = rem >> 3, u = rem & 7;
            cpasync(bufb + 32768 + s * 16384 + SW128(row * 128 + u * 16),
                    &g_ws[s][((tap * 8 + cihi) * 512 + n0 + row) * 64 + u * 8], 16);
        }
        asm volatile("cp.async.commit_group;" ::: "memory");
    };

    issue(0);
    for (int stage = 0; stage < 216; ++stage) {
        if (stage + 1 < 216) {
            issue(stage + 1);
            asm volatile("cp.async.wait_group 1;" ::: "memory");
        } else {
            asm volatile("cp.async.wait_group 0;" ::: "memory");
        }
        __syncthreads();
        uint32_t bufb = sb + (stage & 1) * 65536;

        #pragma unroll
        for (int k16 = 0; k16 < 4; ++k16) {
            const int kb = k16 * 16;
            // ---- batch all 8 fragment loads (pipelined in LSU) ----
            uint32_t b0f[2][4], b1f[2][4], a0f[2][4], a1f[2][4];
            #pragma unroll
            for (int ni = 0; ni < 2; ++ni) {
                uint32_t ad = bufb + 32768 + SW128((n_off + ni * 16 + b_rl) * 128 + (kb + b_ko) * 2);
                ldmx4(b0f[ni][0], b0f[ni][1], b0f[ni][2], b0f[ni][3], ad);
            }
            #pragma unroll
            for (int ni = 0; ni < 2; ++ni) {
                uint32_t ad = bufb + 49152 + SW128((n_off + ni * 16 + b_rl) * 128 + (kb + b_ko) * 2);
                ldmx4(b1f[ni][0], b1f[ni][1], b1f[ni][2], b1f[ni][3], ad);
            }
            #pragma unroll
            for (int mi = 0; mi < 2; ++mi) {
                uint32_t ad = bufb + SW128((m_off + mi * 16 + a_rl) * 128 + (kb + a_ko) * 2);
                ldmx4(a0f[mi][0], a0f[mi][1], a0f[mi][2], a0f[mi][3], ad);
            }
            #pragma unroll
            for (int mi = 0; mi < 2; ++mi) {
                uint32_t ad = bufb + 16384 + SW128((m_off + mi * 16 + a_rl) * 128 + (kb + a_ko) * 2);
                ldmx4(a1f[mi][0], a1f[mi][1], a1f[mi][2], a1f[mi][3], ad);
            }
            // ---- 24 MMAs: 00->accA, 01->accB, 10->accB ----
            #pragma unroll
            for (int mi = 0; mi < 2; ++mi)
                #pragma unroll
                for (int ni = 0; ni < 2; ++ni) {
                    mma16816(accA[mi][2 * ni],     a0f[mi], b0f[ni][0], b0f[ni][1]);
                    mma16816(accA[mi][2 * ni + 1], a0f[mi], b0f[ni][2], b0f[ni][3]);
                    mma16816(accB[mi][2 * ni],     a0f[mi], b1f[ni][0], b1f[ni][1]);
                    mma16816(accB[mi][2 * ni + 1], a0f[mi], b1f[ni][2], b1f[ni][3]);
                    mma16816(accB[mi][2 * ni],     a1f[mi], b0f[ni][0], b0f[ni][1]);
                    mma16816(accB[mi][2 * ni + 1], a1f[mi], b0f[ni][2], b0f[ni][3]);
                }
        }

        // hierarchical merge: accA -> smem outer every 4 stages (own slice, no sync)
        if ((stage & 3) == 3) {
            #pragma unroll
            for (int mi = 0; mi < 2; ++mi)
                #pragma unroll
                for (int nj = 0; nj < 4; ++nj)
                    #pragma unroll
                    for (int r = 0; r < 4; ++r) {
                        int idx = (mi * 16 + nj * 4 + r) * 512 + tid;
                        s_oac[idx] += accA[mi][nj][r];
                        accA[mi][nj][r] = 0.f;
                    }
        }
        __syncthreads();
    }

    #pragma unroll
    for (int mi = 0; mi < 2; ++mi)
        #pragma unroll
        for (int nj = 0; nj < 4; ++nj)
            #pragma unroll
            for (int r = 0; r < 4; ++r) {
                int m  = m0 + m_off + mi * 16 + (lane >> 2) + 8 * (r >> 1);
                int co = n0 + n_off + nj * 8 + ((lane & 3) << 1) + (r & 1);
                float v = s_oac[(mi * 16 + nj * 4 + r) * 512 + tid]
                        + accB[mi][nj][r] * 4.8828125e-4f;  // 2^-11
                g_rpn[m * 512 + co] = fmaxf(v + __ldg(&bias[co]), 0.f);
            }
}

__global__ __launch_bounds__(256) void k_head(const float* __restrict__ bc,
                                              const float* __restrict__ bb,
                                              float* __restrict__ out_bbox) {
    __shared__ float As[16][132];
    __shared__ float Bs[16][48];
    const int tid = threadIdx.x, m0 = blockIdx.x * 128, n0 = blockIdx.y * 48;
    const int tx = tid & 15, ty = tid >> 4, lm = tid >> 1, lkq = (tid & 1) << 2;
    float oac[8][3], cmp[8][3];
    #pragma unroll
    for (int i = 0; i < 8; ++i)
        #pragma unroll
        for (int c = 0; c < 3; ++c) { oac[i][c] = 0.f; cmp[i][c] = 0.f; }
    for (int kk = 0; kk < 32; ++kk) {
        float4 a0 = *(const float4*)&g_rpn[(m0 + lm) * 512 + (kk << 4) + lkq];
        float4 a1 = *(const float4*)&g_rpn[(m0 + lm) * 512 + (kk << 4) + lkq + 8];
        float4 bw = make_float4(0.f, 0.f, 0.f, 0.f);
        int bk = 0, bn = 0;
        if (tid < 192) {
            bk = tid / 12; bn = (tid - bk * 12) << 2;
            bw = *(const float4*)&g_whead[((kk << 4) + bk) * 144 + n0 + bn];
        }
        __syncthreads();
        As[lkq + 0][lm] = a0.x;  As[lkq + 1][lm] = a0.y;  As[lkq + 2][lm] = a0.z;  As[lkq + 3][lm] = a0.w;
        As[lkq + 8][lm] = a1.x;  As[lkq + 9][lm] = a1.y;  As[lkq + 10][lm] = a1.z; As[lkq + 11][lm] = a1.w;
        if (tid < 192) *(float4*)&Bs[bk][bn] = bw;
        __syncthreads();
        float inn[8][3];
        #pragma unroll
        for (int i = 0; i < 8; ++i)
            #pragma unroll
            for (int c = 0; c < 3; ++c) inn[i][c] = 0.f;
        #pragma unroll
        for (int k = 0; k < 16; ++k) {
            float4 av0 = *(const float4*)&As[k][ty << 3];
            float4 av1 = *(const float4*)&As[k][(ty << 3) + 4];
            float b0 = Bs[k][tx * 3], b1 = Bs[k][tx * 3 + 1], b2 = Bs[k][tx * 3 + 2];
            float am[8] = {av0.x, av0.y, av0.z, av0.w, av1.x, av1.y, av1.z, av1.w};
            #pragma unroll
            for (int i = 0; i < 8; ++i) {
                inn[i][0] += am[i] * b0; inn[i][1] += am[i] * b1; inn[i][2] += am[i] * b2;
            }
        }
        #pragma unroll
        for (int i = 0; i < 8; ++i)
            #pragma unroll
            for (int c = 0; c < 3; ++c) {
                float y = inn[i][c] - cmp[i][c], t = oac[i][c] + y;
                cmp[i][c] = (t - oac[i][c]) - y; oac[i][c] = t;
            }
    }
    #pragma unroll
    for (int i = 0; i < 8; ++i) {
        int m = m0 + (ty << 3) + i, b = m / THW, pos = m - b * THW;
        #pragma unroll
        for (int c = 0; c < 3; ++c) {
            int n = n0 + tx * 3 + c;
            float v = oac[i][c] + cmp[i][c];
            if (n < 36) g_cls[(b * 36 + n) * THW + pos] = v + bc[n];
            else        out_bbox[(b * 108 + (n - 36)) * THW + pos] = v + bb[n - 36];
        }
    }
}

__global__ void k_prob(float* __restrict__ out_prob) {
    int i = blockIdx.x * 256 + threadIdx.x;
    if (i >= 8 * NPROP) return;
    int b = i / NPROP, r = i - b * NPROP, pos = r / 18, a = r - pos * 18;
    float s0 = g_cls[(b * 36 + a) * THW + pos];
    float s1 = g_cls[(b * 36 + 18 + a) * THW + pos];
    float mx = fmaxf(s0, s1);
    float e0 = expf(s0 - mx), e1 = expf(s1 - mx), s = e0 + e1;
    out_prob[(b * 36 + a) * THW + pos]      = e0 / s;
    out_prob[(b * 36 + 18 + a) * THW + pos] = e1 / s;
    g_okey[b * NPROP + r] = okey(e1 / s);
}

__global__ void k_prop(const float* __restrict__ anchors, const float* __restrict__ im_info,
                       const float* __restrict__ bbox) {
    int i = blockIdx.x * 256 + threadIdx.x;
    if (i >= 8 * NPROP) return;
    int b = i / NPROP, r = i - b * NPROP, pos = r / 18, a = r - pos * 18;
    const float* an = &anchors[r * 6];
    float aw = an[3] - an[0] + 1.f, ah = an[4] - an[1] + 1.f, al = an[5] - an[2] + 1.f;
    float cx = an[0] + 0.5f * aw, cy = an[1] + 0.5f * ah, ct = an[2] + 0.5f * al;
    const float* dp = &bbox[(b * 108 + a * 6) * THW + pos];
    float pcx = dp[0] * aw + cx, pcy = dp[THW] * ah + cy, pct = dp[2 * THW] * al + ct;
    float pw = expf(dp[3 * THW]) * aw, ph = expf(dp[4 * THW]) * ah, pl = expf(dp[5 * THW]) * al;
    float hx = im_info[b * 3 + 1] - 1.f, hy = im_info[b * 3 + 0] - 1.f;
    float* o = &g_props[(b * NPROP + r) * 6];
    o[0] = fminf(fmaxf(pcx - 0.5f * pw, 0.f), hx);
    o[1] = fminf(fmaxf(pcy - 0.5f * ph, 0.f), hy);
    o[2] = fminf(fmaxf(pct - 0.5f * pl, 0.f), 15.f);
    o[3] = fminf(fmaxf(pcx + 0.5f * pw, 0.f), hx);
    o[4] = fminf(fmaxf(pcy + 0.5f * ph, 0.f), hy);
    o[5] = fminf(fmaxf(pct + 0.5f * pl, 0.f), 15.f);
}

__global__ __launch_bounds__(1024) void k_topk(float* __restrict__ out) {
    const int b = blockIdx.x, tid = threadIdx.x;
    const unsigned* key = g_okey + b * NPROP;
    __shared__ int s_cnt, n_gt, n_eq;
    __shared__ unsigned s_lo, s_hi;
    __shared__ int win[300];
    __shared__ int eq_buf[4096];
    __shared__ unsigned long long skey[512];
    if (tid == 0) { s_lo = 0u; s_hi = 0xFFFFFFFFu; }
    __syncthreads();
    for (int it = 0; it < 32; ++it) {
        unsigned lo = s_lo, hi = s_hi;
        unsigned mid = lo + (unsigned)((((unsigned long long)hi - lo + 1ull)) >> 1);
        if (tid == 0) s_cnt = 0;
        __syncthreads();
        int c = 0;
        for (int i = tid; i < NPROP; i += 1024) c += (key[i] >= mid);
        #pragma unroll
        for (int o = 16; o > 0; o >>= 1) c += __shfl_down_sync(0xffffffffu, c, o);
        if ((tid & 31) == 0) atomicAdd(&s_cnt, c);
        __syncthreads();
        if (tid == 0) { if (s_cnt >= 300) s_lo = mid; else s_hi = mid - 1u; }
        __syncthreads();
    }
    const unsigned V = s_lo;
    if (tid == 0) { n_gt = 0; n_eq = 0; }
    __syncthreads();
    for (int i = tid; i < NPROP; i += 1024) {
        unsigned u = key[i];
        if (u > V)       { int p = atomicAdd(&n_gt, 1); win[p] = i; }
        else if (u == V) { int p = atomicAdd(&n_eq, 1); if (p < 4096) eq_buf[p] = i; }
    }
    __syncthreads();
    const int need = 300 - n_gt;
    const int ne = (n_eq < 4096) ? n_eq : 4096;
    for (int j = tid; j < ne; j += 1024) {
        int v = eq_buf[j], rk = 0;
        for (int q = 0; q < ne; ++q) rk += (eq_buf[q] < v);
        if (rk < need) win[n_gt + rk] = v;
    }
    __syncthreads();
    for (int i = tid; i < 512; i += 1024) {
        if (i < 300) {
            int idx = win[i];
            skey[i] = ((unsigned long long)key[idx] << 32) | (unsigned)(~(unsigned)idx);
        } else skey[i] = 0ull;
    }
    __syncthreads();
    for (int ks = 2; ks <= 512; ks <<= 1)
        for (int js = ks >> 1; js > 0; js >>= 1) {
            if (tid < 512) {
                int i = tid, ixj = i ^ js;
                if (ixj > i) {
                    unsigned long long A = skey[i], B2 = skey[ixj];
                    bool up = (i & ks) == 0;
                    if (up ? (A < B2) : (A > B2)) { skey[i] = B2; skey[ixj] = A; }
                }
            }
            __syncthreads();
        }
    for (int r = tid; r < 300; r += 1024) {
        int idx = (int)(~(unsigned)skey[r]);
        const float* p = &g_props[(b * NPROP + idx) * 6];
        float* o = out + (b * 300 + r) * 7;
        o[0] = (float)b;
        o[1] = p[0]; o[2] = p[1]; o[3] = p[2]; o[4] = p[3]; o[5] = p[4]; o[6] = p[5];
    }
}

extern "C" void kernel_launch(void* const* d_in, const int* in_sizes, int n_in,
                              void* d_out, int out_size) {
    const float* base_feat = (const float*)d_in[0];
    const float* im_info   = (const float*)d_in[1];
    const float* W_conv    = (const float*)d_in[2];
    const float* b_conv    = (const float*)d_in[3];
    const float* W_cls     = (const float*)d_in[4];
    const float* b_cls     = (const float*)d_in[5];
    const float* W_bbox    = (const float*)d_in[6];
    const float* b_bbox    = (const float*)d_in[7];
    const float* anchors   = (const float*)d_in[8];
    float* out = (float*)d_out;

    cudaFuncSetAttribute(k_conv_mma, cudaFuncAttributeMaxDynamicSharedMemorySize, SMEM_CONV);
    k_split_x<<<dim3(150, 16, 8), 256>>>(base_feat);
    k_split_w<<<1024, 256>>>(W_conv);
    k_whead<<<288, 256>>>(W_cls, W_bbox);
    k_conv_mma<<<dim3(300, 4), 512, SMEM_CONV>>>(b_conv);
    k_head<<<dim3(300, 3), 256>>>(b_cls, b_bbox, out + OUT_BBOX);
    k_prob<<<2700, 256>>>(out + OUT_PROB);
    k_prop<<<2700, 256>>>(anchors, im_info, out + OUT_BBOX);
    k_topk<<<8, 1024>>>(out);
}